// round 1
// baseline (speedup 1.0000x reference)
#include <cuda_runtime.h>
#include <math.h>

#define NTOK 2048
#define DM   512
#define NH   8
#define DH   64
#define CND  768
#define PAD  68   // 64 + 4 float pad per neighborhood row (bank-conflict free)

// -------- scratch (device globals; no allocation allowed) --------
__device__ float g_nscale[2 * DM];            // cond @ w_cond.T + 1
__device__ float g_rstd[NTOK];                // rsqrt(mean(x^2)+eps)
__device__ float g_q[2 * NH * 1024 * DH];     // [n][h][ij][d]
__device__ float g_k[2 * NH * 1024 * DH];
__device__ float g_v[2 * NH * 1024 * DH];
__device__ float g_o[NTOK * DM];              // attention out, [t][h*64+d]

// ================= k1: norm_scale = cond @ w_cond.T + 1 =================
__global__ void k_cond(const float* __restrict__ cond,
                       const float* __restrict__ w_cond) {
    int w    = (blockIdx.x * blockDim.x + threadIdx.x) >> 5;
    int lane = threadIdx.x & 31;
    if (w >= 2 * DM) return;
    int n = w >> 9, c = w & 511;
    const float* cp = cond + n * CND;
    const float* wp = w_cond + c * CND;
    float s = 0.f;
    #pragma unroll 4
    for (int k = lane; k < CND; k += 32) s += cp[k] * wp[k];
    #pragma unroll
    for (int o = 16; o; o >>= 1) s += __shfl_xor_sync(~0u, s, o);
    if (!lane) g_nscale[w] = s + 1.0f;
}

// ================= k2: per-token rstd =================
__global__ void k_rms(const float* __restrict__ x) {
    int w    = (blockIdx.x * blockDim.x + threadIdx.x) >> 5;
    int lane = threadIdx.x & 31;
    if (w >= NTOK) return;
    const float4* xp = (const float4*)(x + w * DM);
    float s = 0.f;
    #pragma unroll
    for (int i = 0; i < 4; i++) {
        float4 v = xp[i * 32 + lane];
        s += v.x * v.x + v.y * v.y + v.z * v.z + v.w * v.w;
    }
    #pragma unroll
    for (int o = 16; o; o >>= 1) s += __shfl_xor_sync(~0u, s, o);
    if (!lane) g_rstd[w] = rsqrtf(s * (1.0f / DM) + 1e-6f);
}

// ====== k3: QKV GEMM. A[t][k] = x*rstd*nscale, B = w_qkv. 128x128x16 tile ======
__global__ __launch_bounds__(256) void k_qkv(const float* __restrict__ x,
                                             const float* __restrict__ w) {
    __shared__ float As[16][128];
    __shared__ float Bs[16][128];
    int m0 = blockIdx.y * 128, n0 = blockIdx.x * 128;
    int tid = threadIdx.x;
    int ty = tid >> 4, tx = tid & 15;
    int nb = m0 >> 10;  // batch of this row-tile (1024 tokens per batch)
    const float* nsc = g_nscale + nb * DM;

    float acc[8][8];
    #pragma unroll
    for (int i = 0; i < 8; i++)
        #pragma unroll
        for (int j = 0; j < 8; j++) acc[i][j] = 0.f;

    for (int k0 = 0; k0 < DM; k0 += 16) {
        #pragma unroll
        for (int i = 0; i < 2; i++) {
            int f = tid + i * 256;
            int row = f >> 2, kc = (f & 3) * 4;
            float4 a = *(const float4*)(x + (size_t)(m0 + row) * DM + k0 + kc);
            float r = g_rstd[m0 + row];
            As[kc + 0][row] = a.x * r * nsc[k0 + kc + 0];
            As[kc + 1][row] = a.y * r * nsc[k0 + kc + 1];
            As[kc + 2][row] = a.z * r * nsc[k0 + kc + 2];
            As[kc + 3][row] = a.w * r * nsc[k0 + kc + 3];
            float4 b = *(const float4*)(w + (size_t)(n0 + row) * DM + k0 + kc);
            Bs[kc + 0][row] = b.x;
            Bs[kc + 1][row] = b.y;
            Bs[kc + 2][row] = b.z;
            Bs[kc + 3][row] = b.w;
        }
        __syncthreads();
        #pragma unroll
        for (int kk = 0; kk < 16; kk++) {
            float4 a0 = *(float4*)&As[kk][ty * 8];
            float4 a1 = *(float4*)&As[kk][ty * 8 + 4];
            float4 b0 = *(float4*)&Bs[kk][tx * 8];
            float4 b1 = *(float4*)&Bs[kk][tx * 8 + 4];
            float a[8] = {a0.x, a0.y, a0.z, a0.w, a1.x, a1.y, a1.z, a1.w};
            float b[8] = {b0.x, b0.y, b0.z, b0.w, b1.x, b1.y, b1.z, b1.w};
            #pragma unroll
            for (int i = 0; i < 8; i++)
                #pragma unroll
                for (int j = 0; j < 8; j++) acc[i][j] += a[i] * b[j];
        }
        __syncthreads();
    }

    // scatter epilogue into q/k/v head-major buffers
    int cbase = n0 + tx * 8;
    int part  = cbase >> 9;
    int head  = (cbase >> 6) & 7;
    int d0    = cbase & 63;
    float* dst = (part == 0) ? g_q : (part == 1) ? g_k : g_v;
    dst += (size_t)((nb * NH + head) * 1024) * DH + d0;
    #pragma unroll
    for (int i = 0; i < 8; i++) {
        int t  = m0 + ty * 8 + i;
        int ij = t & 1023;
        float4 v0 = {acc[i][0], acc[i][1], acc[i][2], acc[i][3]};
        float4 v1 = {acc[i][4], acc[i][5], acc[i][6], acc[i][7]};
        *(float4*)(dst + (size_t)ij * DH)     = v0;
        *(float4*)(dst + (size_t)ij * DH + 4) = v1;
    }
}

// ====== k4: per-head L2 norm (sqrt(scale)*rsqrt(sum^2+eps)) + RoPE ======
__global__ void k_rope(const float* __restrict__ pos,
                       const float* __restrict__ scale) {
    int w    = (blockIdx.x * blockDim.x + threadIdx.x) >> 5;
    int lane = threadIdx.x & 31;
    const int total = 2 * NH * 1024;
    if (w >= 2 * total) return;
    float* buf = (w < total) ? g_q : g_k;
    int v  = (w < total) ? w : w - total;
    int n  = v >> 13;
    int h  = (v >> 10) & 7;
    int ij = v & 1023;
    float* p = buf + (size_t)v * DH;

    float a = p[lane];        // dims 0..31
    float b = p[lane + 32];   // dims 32..63
    float s = a * a + b * b;
    #pragma unroll
    for (int o = 16; o; o >>= 1) s += __shfl_xor_sync(~0u, s, o);
    float fac = sqrtf(scale[h]) * rsqrtf(s + 1e-6f);
    a *= fac;
    b *= fac;

    // RoPE over the first 32 dims: pairs (m, m+16), m in [0,16)
    int m = lane & 15;
    float freq = 3.14159265358979f * expf((float)(m * 8 + h) * (2.302585092994046f / 128.0f));
    float th = pos[n * 1024 + ij] * freq;
    float sn, cs;
    sincosf(th, &sn, &cs);
    float partner = __shfl_xor_sync(~0u, a, 16);
    float na = (lane < 16) ? (a * cs - partner * sn) : (a * cs + partner * sn);
    p[lane]      = na;
    p[lane + 32] = b;
}

// ====== k5: 7x7 neighborhood attention. block = (n, head, 8x8 tile) ======
__global__ __launch_bounds__(256) void k_attn() {
    extern __shared__ float sm[];
    float* Ks = sm;                 // [196][PAD]
    float* Vs = sm + 196 * PAD;
    int b    = blockIdx.x;
    int tile = b & 15;
    int h    = (b >> 4) & 7;
    int n    = b >> 7;
    int i0 = (tile >> 2) * 8, j0 = (tile & 3) * 8;
    int rbase = min(max(i0 - 3, 0), 18);
    int cbase = min(max(j0 - 3, 0), 18);

    const float* kb = g_k + (size_t)((n * NH + h) * 1024) * DH;
    const float* vb = g_v + (size_t)((n * NH + h) * 1024) * DH;

    // stage 14x14 neighborhood of K and V (coalesced along d)
    for (int idx = threadIdx.x; idx < 196 * 16; idx += 256) {
        int px = idx >> 4, u = idx & 15;
        int r = px / 14, cc = px - r * 14;
        int g = ((rbase + r) * 32 + cbase + cc) * 16 + u;  // float4 index
        ((float4*)(Ks + px * PAD))[u] = ((const float4*)kb)[g];
        ((float4*)(Vs + px * PAD))[u] = ((const float4*)vb)[g];
    }
    __syncthreads();

    int p = threadIdx.x >> 2, s = threadIdx.x & 3;  // pixel, dim-quarter
    int gi = i0 + (p >> 3), gj = j0 + (p & 7);
    int si = min(max(gi - 3, 0), 25) - rbase;
    int sj = min(max(gj - 3, 0), 25) - cbase;

    const float* qp = g_q + ((size_t)((n * NH + h) * 1024) + gi * 32 + gj) * DH + s * 16;
    float4 q0 = ((const float4*)qp)[0];
    float4 q1 = ((const float4*)qp)[1];
    float4 q2 = ((const float4*)qp)[2];
    float4 q3 = ((const float4*)qp)[3];

    float logit[49];
    #pragma unroll
    for (int a = 0; a < 7; a++) {
        #pragma unroll
        for (int bb = 0; bb < 7; bb++) {
            const float* kp = Ks + ((si + a) * 14 + sj + bb) * PAD + s * 16;
            float4 c0 = ((const float4*)kp)[0];
            float4 c1 = ((const float4*)kp)[1];
            float4 c2 = ((const float4*)kp)[2];
            float4 c3 = ((const float4*)kp)[3];
            float d = q0.x * c0.x + q0.y * c0.y + q0.z * c0.z + q0.w * c0.w
                    + q1.x * c1.x + q1.y * c1.y + q1.z * c1.z + q1.w * c1.w
                    + q2.x * c2.x + q2.y * c2.y + q2.z * c2.z + q2.w * c2.w
                    + q3.x * c3.x + q3.y * c3.y + q3.z * c3.z + q3.w * c3.w;
            d += __shfl_xor_sync(~0u, d, 1);
            d += __shfl_xor_sync(~0u, d, 2);
            logit[a * 7 + bb] = d;
        }
    }

    float mx = -1e30f;
    #pragma unroll
    for (int i = 0; i < 49; i++) mx = fmaxf(mx, logit[i]);
    float sum = 0.f;
    #pragma unroll
    for (int i = 0; i < 49; i++) {
        float e = __expf(logit[i] - mx);
        logit[i] = e;
        sum += e;
    }
    float inv = 1.0f / sum;

    float acc[16];
    #pragma unroll
    for (int j = 0; j < 16; j++) acc[j] = 0.f;
    #pragma unroll
    for (int a = 0; a < 7; a++) {
        #pragma unroll
        for (int bb = 0; bb < 7; bb++) {
            float wgt = logit[a * 7 + bb];
            const float* vp = Vs + ((si + a) * 14 + sj + bb) * PAD + s * 16;
            #pragma unroll
            for (int j = 0; j < 16; j++) acc[j] += wgt * vp[j];
        }
    }

    float* op = g_o + (size_t)(n * 1024 + gi * 32 + gj) * DM + h * DH + s * 16;
    #pragma unroll
    for (int u = 0; u < 4; u++) {
        float4 o4 = {acc[u * 4 + 0] * inv, acc[u * 4 + 1] * inv,
                     acc[u * 4 + 2] * inv, acc[u * 4 + 3] * inv};
        ((float4*)op)[u] = o4;
    }
}

// ====== k6: out = o @ w_out.T + x. 64x64x16 tile ======
__global__ __launch_bounds__(256) void k_out(const float* __restrict__ w,
                                             const float* __restrict__ x,
                                             float* __restrict__ out) {
    __shared__ float As[16][64];
    __shared__ float Bs[16][64];
    int m0 = blockIdx.y * 64, n0 = blockIdx.x * 64;
    int tid = threadIdx.x;
    int ty = tid >> 4, tx = tid & 15;

    float acc[4][4];
    #pragma unroll
    for (int i = 0; i < 4; i++)
        #pragma unroll
        for (int j = 0; j < 4; j++) acc[i][j] = 0.f;

    int row = tid >> 2, kc = (tid & 3) * 4;
    for (int k0 = 0; k0 < DM; k0 += 16) {
        float4 a = *(const float4*)(g_o + (size_t)(m0 + row) * DM + k0 + kc);
        As[kc + 0][row] = a.x;
        As[kc + 1][row] = a.y;
        As[kc + 2][row] = a.z;
        As[kc + 3][row] = a.w;
        float4 b = *(const float4*)(w + (size_t)(n0 + row) * DM + k0 + kc);
        Bs[kc + 0][row] = b.x;
        Bs[kc + 1][row] = b.y;
        Bs[kc + 2][row] = b.z;
        Bs[kc + 3][row] = b.w;
        __syncthreads();
        #pragma unroll
        for (int kk = 0; kk < 16; kk++) {
            float4 a4 = *(float4*)&As[kk][ty * 4];
            float4 b4 = *(float4*)&Bs[kk][tx * 4];
            float av[4] = {a4.x, a4.y, a4.z, a4.w};
            float bv[4] = {b4.x, b4.y, b4.z, b4.w};
            #pragma unroll
            for (int i = 0; i < 4; i++)
                #pragma unroll
                for (int j = 0; j < 4; j++) acc[i][j] += av[i] * bv[j];
        }
        __syncthreads();
    }

    #pragma unroll
    for (int i = 0; i < 4; i++) {
        int t = m0 + ty * 4 + i;
        int c0 = n0 + tx * 4;
        float4 sk = *(const float4*)(x + (size_t)t * DM + c0);
        float4 o4 = {acc[i][0] + sk.x, acc[i][1] + sk.y,
                     acc[i][2] + sk.z, acc[i][3] + sk.w};
        *(float4*)(out + (size_t)t * DM + c0) = o4;
    }
}

// =========================== launch ===========================
extern "C" void kernel_launch(void* const* d_in, const int* in_sizes, int n_in,
                              void* d_out, int out_size) {
    const float* x      = (const float*)d_in[0];
    const float* pos    = (const float*)d_in[1];
    const float* cond   = (const float*)d_in[2];
    const float* w_cond = (const float*)d_in[3];
    const float* w_qkv  = (const float*)d_in[4];
    const float* scale  = (const float*)d_in[5];
    const float* w_out  = (const float*)d_in[6];
    float* out = (float*)d_out;

    const int attn_smem = 2 * 196 * PAD * 4;  // 106624 B
    cudaFuncSetAttribute(k_attn, cudaFuncAttributeMaxDynamicSharedMemorySize,
                         attn_smem);

    k_cond<<<128, 256>>>(cond, w_cond);
    k_rms<<<256, 256>>>(x);
    dim3 g3(12, 16);
    k_qkv<<<g3, 256>>>(x, w_qkv);
    k_rope<<<4096, 256>>>(pos, scale);
    k_attn<<<256, 256, attn_smem>>>();
    dim3 g6(8, 32);
    k_out<<<g6, 256>>>(w_out, x, out);
}

// round 3
// speedup vs baseline: 1.2054x; 1.2054x over previous
#include <cuda_runtime.h>
#include <math.h>
#include <stdint.h>

#define NTOK 2048
#define DM   512
#define NH   8
#define DH   64
#define CND  768
#define PAD  68

// -------- scratch (device globals; no allocation allowed) --------
__device__ float g_nscale[2 * DM];
__device__ float g_rstd[NTOK];
__device__ float g_q[2 * NH * 1024 * DH];
__device__ float g_k[2 * NH * 1024 * DH];
__device__ float g_v[2 * NH * 1024 * DH];
__device__ float g_o[NTOK * DM];

// ---------------- mma helpers ----------------
__device__ __forceinline__ void mma_tf32(float d[4], const uint32_t a[4],
                                         const uint32_t b[2]) {
    asm("mma.sync.aligned.m16n8k8.row.col.f32.tf32.tf32.f32 "
        "{%0,%1,%2,%3}, {%4,%5,%6,%7}, {%8,%9}, {%0,%1,%2,%3};\n"
        : "+f"(d[0]), "+f"(d[1]), "+f"(d[2]), "+f"(d[3])
        : "r"(a[0]), "r"(a[1]), "r"(a[2]), "r"(a[3]), "r"(b[0]), "r"(b[1]));
}

__device__ __forceinline__ uint32_t to_tf32(float v) {
    uint32_t r;
    asm("cvt.rna.tf32.f32 %0, %1;" : "=r"(r) : "f"(v));
    return r;
}

__device__ __forceinline__ void split_tf32(float v, uint32_t& hi, uint32_t& lo) {
    hi = to_tf32(v);
    lo = to_tf32(v - __uint_as_float(hi));
}

// ================= k1: norm_scale = cond @ w_cond.T + 1 =================
__global__ void k_cond(const float* __restrict__ cond,
                       const float* __restrict__ w_cond) {
    int w    = (blockIdx.x * blockDim.x + threadIdx.x) >> 5;
    int lane = threadIdx.x & 31;
    if (w >= 2 * DM) return;
    int n = w >> 9, c = w & 511;
    const float* cp = cond + n * CND;
    const float* wp = w_cond + c * CND;
    float s = 0.f;
    #pragma unroll 4
    for (int k = lane; k < CND; k += 32) s += cp[k] * wp[k];
    #pragma unroll
    for (int o = 16; o; o >>= 1) s += __shfl_xor_sync(~0u, s, o);
    if (!lane) g_nscale[w] = s + 1.0f;
}

// ================= k2: per-token rstd =================
__global__ void k_rms(const float* __restrict__ x) {
    int w    = (blockIdx.x * blockDim.x + threadIdx.x) >> 5;
    int lane = threadIdx.x & 31;
    if (w >= NTOK) return;
    const float4* xp = (const float4*)(x + w * DM);
    float s = 0.f;
    #pragma unroll
    for (int i = 0; i < 4; i++) {
        float4 v = xp[i * 32 + lane];
        s += v.x * v.x + v.y * v.y + v.z * v.z + v.w * v.w;
    }
    #pragma unroll
    for (int o = 16; o; o >>= 1) s += __shfl_xor_sync(~0u, s, o);
    if (!lane) g_rstd[w] = rsqrtf(s * (1.0f / DM) + 1e-6f);
}

// ====== k3: QKV GEMM with 3xTF32 tensor-core MMA ======
// C[2048][1536] = A @ W^T, A scaled by rstd*nscale at smem-store time.
// BM=128 BN=128 BK=16, 8 warps in 2(m)x4(n), warp tile 64x32.
__global__ __launch_bounds__(256) void k_qkv_t(const float* __restrict__ x,
                                               const float* __restrict__ w) {
    __shared__ float As[2][128][9];   // [k-chunk][row m][k-in-chunk], pad->9
    __shared__ float Bs[2][128][9];   // [k-chunk][row n][k-in-chunk]
    const int tid = threadIdx.x;
    const int m0 = blockIdx.y * 128, n0 = blockIdx.x * 128;
    const int nb = m0 >> 10;
    const float* nsc = g_nscale + nb * DM;

    int rowA[2], kcA[2];
    float rstdv[2];
    #pragma unroll
    for (int i = 0; i < 2; i++) {
        int f = tid + i * 256;
        rowA[i] = f >> 2;
        kcA[i]  = (f & 3) * 4;
        rstdv[i] = g_rstd[m0 + rowA[i]];
    }

    const int lane = tid & 31, wid = tid >> 5;
    const int mbase = (wid >> 2) * 64, nbase = (wid & 3) * 32;
    const int qy = lane >> 2, t4 = lane & 3;

    float acc[4][4][4];
    #pragma unroll
    for (int i = 0; i < 4; i++)
        #pragma unroll
        for (int j = 0; j < 4; j++)
            #pragma unroll
            for (int r = 0; r < 4; r++) acc[i][j][r] = 0.f;

    float4 pa[2], pb[2];
    #pragma unroll
    for (int i = 0; i < 2; i++) {
        pa[i] = *(const float4*)(x + (size_t)(m0 + rowA[i]) * DM + kcA[i]);
        pb[i] = *(const float4*)(w + (size_t)(n0 + rowA[i]) * DM + kcA[i]);
    }

    for (int it = 0; it < DM / 16; it++) {
        int k0 = it * 16;
        #pragma unroll
        for (int i = 0; i < 2; i++) {
            int ch = kcA[i] >> 3, kk = kcA[i] & 7;
            float* da = &As[ch][rowA[i]][kk];
            float r = rstdv[i];
            da[0] = pa[i].x * r * nsc[k0 + kcA[i] + 0];
            da[1] = pa[i].y * r * nsc[k0 + kcA[i] + 1];
            da[2] = pa[i].z * r * nsc[k0 + kcA[i] + 2];
            da[3] = pa[i].w * r * nsc[k0 + kcA[i] + 3];
            float* db = &Bs[ch][rowA[i]][kk];
            db[0] = pb[i].x; db[1] = pb[i].y; db[2] = pb[i].z; db[3] = pb[i].w;
        }
        __syncthreads();
        if (it + 1 < DM / 16) {
            int k1 = k0 + 16;
            #pragma unroll
            for (int i = 0; i < 2; i++) {
                pa[i] = *(const float4*)(x + (size_t)(m0 + rowA[i]) * DM + k1 + kcA[i]);
                pb[i] = *(const float4*)(w + (size_t)(n0 + rowA[i]) * DM + k1 + kcA[i]);
            }
        }
        #pragma unroll
        for (int cc = 0; cc < 2; cc++) {
            uint32_t ah[4][4], al[4][4], bh[4][2], bl[4][2];
            #pragma unroll
            for (int mt = 0; mt < 4; mt++) {
                int r = mbase + mt * 16 + qy;
                split_tf32(As[cc][r][t4],         ah[mt][0], al[mt][0]);
                split_tf32(As[cc][r + 8][t4],     ah[mt][1], al[mt][1]);
                split_tf32(As[cc][r][t4 + 4],     ah[mt][2], al[mt][2]);
                split_tf32(As[cc][r + 8][t4 + 4], ah[mt][3], al[mt][3]);
            }
            #pragma unroll
            for (int nt = 0; nt < 4; nt++) {
                int r = nbase + nt * 8 + qy;
                split_tf32(Bs[cc][r][t4],     bh[nt][0], bl[nt][0]);
                split_tf32(Bs[cc][r][t4 + 4], bh[nt][1], bl[nt][1]);
            }
            #pragma unroll
            for (int mt = 0; mt < 4; mt++)
                #pragma unroll
                for (int nt = 0; nt < 4; nt++) {
                    mma_tf32(acc[mt][nt], ah[mt], bh[nt]);
                    mma_tf32(acc[mt][nt], al[mt], bh[nt]);
                    mma_tf32(acc[mt][nt], ah[mt], bl[nt]);
                }
        }
        __syncthreads();
    }

    // epilogue: scatter into head-major q/k/v
    int part = n0 >> 9;
    float* base = (part == 0) ? g_q : (part == 1) ? g_k : g_v;
    #pragma unroll
    for (int mt = 0; mt < 4; mt++) {
        int r0 = m0 + mbase + mt * 16 + qy;
        int ij0 = r0 & 1023, ij1 = (r0 + 8) & 1023;
        #pragma unroll
        for (int nt = 0; nt < 4; nt++) {
            int col  = n0 + nbase + nt * 8 + 2 * t4;
            int head = (col >> 6) & 7;
            int d0   = col & 63;
            float* dst = base + ((size_t)(nb * NH + head) * 1024) * DH + d0;
            float2 v0 = {acc[mt][nt][0], acc[mt][nt][1]};
            float2 v1 = {acc[mt][nt][2], acc[mt][nt][3]};
            *(float2*)(dst + (size_t)ij0 * DH) = v0;
            *(float2*)(dst + (size_t)ij1 * DH) = v1;
        }
    }
}

// ====== k4: per-head L2 norm + RoPE ======
__global__ void k_rope(const float* __restrict__ pos,
                       const float* __restrict__ scale) {
    int w    = (blockIdx.x * blockDim.x + threadIdx.x) >> 5;
    int lane = threadIdx.x & 31;
    const int total = 2 * NH * 1024;
    if (w >= 2 * total) return;
    float* buf = (w < total) ? g_q : g_k;
    int v  = (w < total) ? w : w - total;
    int n  = v >> 13;
    int h  = (v >> 10) & 7;
    int ij = v & 1023;
    float* p = buf + (size_t)v * DH;

    float a = p[lane];
    float b = p[lane + 32];
    float s = a * a + b * b;
    #pragma unroll
    for (int o = 16; o; o >>= 1) s += __shfl_xor_sync(~0u, s, o);
    float fac = sqrtf(scale[h]) * rsqrtf(s + 1e-6f);
    a *= fac;
    b *= fac;

    int m = lane & 15;
    float freq = 3.14159265358979f * __expf((float)(m * 8 + h) * (2.302585092994046f / 128.0f));
    float th = pos[n * 1024 + ij] * freq;
    float sn, cs;
    __sincosf(th, &sn, &cs);
    float partner = __shfl_xor_sync(~0u, a, 16);
    float na = (lane < 16) ? (a * cs - partner * sn) : (a * cs + partner * sn);
    p[lane]      = na;
    p[lane + 32] = b;
}

// ====== k5: 7x7 neighborhood attention (fp32) ======
__global__ __launch_bounds__(256) void k_attn() {
    extern __shared__ float sm[];
    float* Ks = sm;
    float* Vs = sm + 196 * PAD;
    int b    = blockIdx.x;
    int tile = b & 15;
    int h    = (b >> 4) & 7;
    int n    = b >> 7;
    int i0 = (tile >> 2) * 8, j0 = (tile & 3) * 8;
    int rbase = min(max(i0 - 3, 0), 18);
    int cbase = min(max(j0 - 3, 0), 18);

    const float* kb = g_k + (size_t)((n * NH + h) * 1024) * DH;
    const float* vb = g_v + (size_t)((n * NH + h) * 1024) * DH;

    for (int idx = threadIdx.x; idx < 196 * 16; idx += 256) {
        int px = idx >> 4, u = idx & 15;
        int r = px / 14, cc = px - r * 14;
        int g = ((rbase + r) * 32 + cbase + cc) * 16 + u;
        ((float4*)(Ks + px * PAD))[u] = ((const float4*)kb)[g];
        ((float4*)(Vs + px * PAD))[u] = ((const float4*)vb)[g];
    }
    __syncthreads();

    int p = threadIdx.x >> 2, s = threadIdx.x & 3;
    int gi = i0 + (p >> 3), gj = j0 + (p & 7);
    int si = min(max(gi - 3, 0), 25) - rbase;
    int sj = min(max(gj - 3, 0), 25) - cbase;

    const float* qp = g_q + ((size_t)((n * NH + h) * 1024) + gi * 32 + gj) * DH + s * 16;
    float4 q0 = ((const float4*)qp)[0];
    float4 q1 = ((const float4*)qp)[1];
    float4 q2 = ((const float4*)qp)[2];
    float4 q3 = ((const float4*)qp)[3];

    float logit[49];
    #pragma unroll
    for (int a = 0; a < 7; a++) {
        #pragma unroll
        for (int bb = 0; bb < 7; bb++) {
            const float* kp = Ks + ((si + a) * 14 + sj + bb) * PAD + s * 16;
            float4 c0 = ((const float4*)kp)[0];
            float4 c1 = ((const float4*)kp)[1];
            float4 c2 = ((const float4*)kp)[2];
            float4 c3 = ((const float4*)kp)[3];
            float d = q0.x * c0.x + q0.y * c0.y + q0.z * c0.z + q0.w * c0.w
                    + q1.x * c1.x + q1.y * c1.y + q1.z * c1.z + q1.w * c1.w
                    + q2.x * c2.x + q2.y * c2.y + q2.z * c2.z + q2.w * c2.w
                    + q3.x * c3.x + q3.y * c3.y + q3.z * c3.z + q3.w * c3.w;
            d += __shfl_xor_sync(~0u, d, 1);
            d += __shfl_xor_sync(~0u, d, 2);
            logit[a * 7 + bb] = d;
        }
    }

    float mx = -1e30f;
    #pragma unroll
    for (int i = 0; i < 49; i++) mx = fmaxf(mx, logit[i]);
    float sum = 0.f;
    #pragma unroll
    for (int i = 0; i < 49; i++) {
        float e = __expf(logit[i] - mx);
        logit[i] = e;
        sum += e;
    }
    float inv = 1.0f / sum;

    float acc[16];
    #pragma unroll
    for (int j = 0; j < 16; j++) acc[j] = 0.f;
    #pragma unroll
    for (int a = 0; a < 7; a++) {
        #pragma unroll
        for (int bb = 0; bb < 7; bb++) {
            float wgt = logit[a * 7 + bb];
            const float* vp = Vs + ((si + a) * 14 + sj + bb) * PAD + s * 16;
            #pragma unroll
            for (int j = 0; j < 16; j++) acc[j] += wgt * vp[j];
        }
    }

    float* op = g_o + (size_t)(n * 1024 + gi * 32 + gj) * DM + h * DH + s * 16;
    #pragma unroll
    for (int u = 0; u < 4; u++) {
        float4 o4 = {acc[u * 4 + 0] * inv, acc[u * 4 + 1] * inv,
                     acc[u * 4 + 2] * inv, acc[u * 4 + 3] * inv};
        ((float4*)op)[u] = o4;
    }
}

// ====== k6: out = o @ w_out.T + skip, 1xTF32 tensor MMA ======
// BM=128 BN=64 BK=16, 8 warps 2(m)x4(n), warp tile 64x16.
__global__ __launch_bounds__(256) void k_out_t(const float* __restrict__ w,
                                               const float* __restrict__ x,
                                               float* __restrict__ out) {
    __shared__ float As[2][128][9];
    __shared__ float Bs[2][64][9];
    const int tid = threadIdx.x;
    const int m0 = blockIdx.y * 128, n0 = blockIdx.x * 64;

    int rowA[2], kcA[2];
    #pragma unroll
    for (int i = 0; i < 2; i++) {
        int f = tid + i * 256;
        rowA[i] = f >> 2;
        kcA[i]  = (f & 3) * 4;
    }
    int rowB = tid >> 2, kcB = (tid & 3) * 4;

    const int lane = tid & 31, wid = tid >> 5;
    const int mbase = (wid >> 2) * 64, nbase = (wid & 3) * 16;
    const int qy = lane >> 2, t4 = lane & 3;

    float acc[4][2][4];
    #pragma unroll
    for (int i = 0; i < 4; i++)
        #pragma unroll
        for (int j = 0; j < 2; j++)
            #pragma unroll
            for (int r = 0; r < 4; r++) acc[i][j][r] = 0.f;

    float4 pa[2], pb;
    #pragma unroll
    for (int i = 0; i < 2; i++)
        pa[i] = *(const float4*)(g_o + (size_t)(m0 + rowA[i]) * DM + kcA[i]);
    pb = *(const float4*)(w + (size_t)(n0 + rowB) * DM + kcB);

    for (int it = 0; it < DM / 16; it++) {
        int k0 = it * 16;
        #pragma unroll
        for (int i = 0; i < 2; i++) {
            int ch = kcA[i] >> 3, kk = kcA[i] & 7;
            float* da = &As[ch][rowA[i]][kk];
            da[0] = pa[i].x; da[1] = pa[i].y; da[2] = pa[i].z; da[3] = pa[i].w;
        }
        {
            int ch = kcB >> 3, kk = kcB & 7;
            float* db = &Bs[ch][rowB][kk];
            db[0] = pb.x; db[1] = pb.y; db[2] = pb.z; db[3] = pb.w;
        }
        __syncthreads();
        if (it + 1 < DM / 16) {
            int k1 = k0 + 16;
            #pragma unroll
            for (int i = 0; i < 2; i++)
                pa[i] = *(const float4*)(g_o + (size_t)(m0 + rowA[i]) * DM + k1 + kcA[i]);
            pb = *(const float4*)(w + (size_t)(n0 + rowB) * DM + k1 + kcB);
        }
        #pragma unroll
        for (int cc = 0; cc < 2; cc++) {
            uint32_t a[4][4], bfr[2][2];
            #pragma unroll
            for (int mt = 0; mt < 4; mt++) {
                int r = mbase + mt * 16 + qy;
                a[mt][0] = to_tf32(As[cc][r][t4]);
                a[mt][1] = to_tf32(As[cc][r + 8][t4]);
                a[mt][2] = to_tf32(As[cc][r][t4 + 4]);
                a[mt][3] = to_tf32(As[cc][r + 8][t4 + 4]);
            }
            #pragma unroll
            for (int nt = 0; nt < 2; nt++) {
                int r = nbase + nt * 8 + qy;
                bfr[nt][0] = to_tf32(Bs[cc][r][t4]);
                bfr[nt][1] = to_tf32(Bs[cc][r][t4 + 4]);
            }
            #pragma unroll
            for (int mt = 0; mt < 4; mt++)
                #pragma unroll
                for (int nt = 0; nt < 2; nt++)
                    mma_tf32(acc[mt][nt], a[mt], bfr[nt]);
        }
        __syncthreads();
    }

    #pragma unroll
    for (int mt = 0; mt < 4; mt++) {
        int r0 = m0 + mbase + mt * 16 + qy;
        #pragma unroll
        for (int nt = 0; nt < 2; nt++) {
            int col = n0 + nbase + nt * 8 + 2 * t4;
            float2 s0 = *(const float2*)(x + (size_t)r0 * DM + col);
            float2 s1 = *(const float2*)(x + (size_t)(r0 + 8) * DM + col);
            float2 v0 = {acc[mt][nt][0] + s0.x, acc[mt][nt][1] + s0.y};
            float2 v1 = {acc[mt][nt][2] + s1.x, acc[mt][nt][3] + s1.y};
            *(float2*)(out + (size_t)r0 * DM + col)       = v0;
            *(float2*)(out + (size_t)(r0 + 8) * DM + col) = v1;
        }
    }
}

// =========================== launch ===========================
extern "C" void kernel_launch(void* const* d_in, const int* in_sizes, int n_in,
                              void* d_out, int out_size) {
    const float* x      = (const float*)d_in[0];
    const float* pos    = (const float*)d_in[1];
    const float* cond   = (const float*)d_in[2];
    const float* w_cond = (const float*)d_in[3];
    const float* w_qkv  = (const float*)d_in[4];
    const float* scale  = (const float*)d_in[5];
    const float* w_out  = (const float*)d_in[6];
    float* out = (float*)d_out;

    const int attn_smem = 2 * 196 * PAD * 4;
    cudaFuncSetAttribute(k_attn, cudaFuncAttributeMaxDynamicSharedMemorySize,
                         attn_smem);

    k_cond<<<128, 256>>>(cond, w_cond);
    k_rms<<<256, 256>>>(x);
    dim3 g3(12, 16);
    k_qkv_t<<<g3, 256>>>(x, w_qkv);
    k_rope<<<4096, 256>>>(pos, scale);
    k_attn<<<256, 256, attn_smem>>>();
    dim3 g6(8, 16);
    k_out_t<<<g6, 256>>>(w_out, x, out);
}

// round 6
// speedup vs baseline: 1.8773x; 1.5574x over previous
#include <cuda_runtime.h>
#include <cuda_bf16.h>
#include <math.h>
#include <stdint.h>

#define NTOK 2048
#define DM   512
#define NH   8
#define DH   64
#define CND  768
#define PAD  68

// -------- scratch (device globals; no allocation allowed) --------
__device__ float g_nscale[2 * DM];
__device__ __align__(16) float g_q[2 * NH * 1024 * DH];
__device__ __align__(16) float g_k[2 * NH * 1024 * DH];
__device__ __align__(16) float g_v[2 * NH * 1024 * DH];
__device__ __align__(16) float g_o[NTOK * DM];
// bf16 hi/lo planes
__device__ __align__(16) __nv_bfloat16 g_ah[NTOK * DM];
__device__ __align__(16) __nv_bfloat16 g_al[NTOK * DM];
__device__ __align__(16) __nv_bfloat16 g_bh[3 * DM * DM];
__device__ __align__(16) __nv_bfloat16 g_bl[3 * DM * DM];

// ---------------- helpers ----------------
__device__ __forceinline__ uint32_t smem_u32(const void* p) {
    uint32_t a;
    asm("{ .reg .u64 t; cvta.to.shared.u64 t, %1; cvt.u32.u64 %0, t; }"
        : "=r"(a) : "l"(p));
    return a;
}
__device__ __forceinline__ uint32_t pack2(__nv_bfloat16 a, __nv_bfloat16 b) {
    __nv_bfloat162 t = __halves2bfloat162(a, b);
    return *reinterpret_cast<uint32_t*>(&t);
}
__device__ __forceinline__ void split2(float a, float b, uint32_t& h, uint32_t& l) {
    __nv_bfloat16 ha = __float2bfloat16_rn(a), hb = __float2bfloat16_rn(b);
    h = pack2(ha, hb);
    l = pack2(__float2bfloat16_rn(a - __bfloat162float(ha)),
              __float2bfloat16_rn(b - __bfloat162float(hb)));
}
__device__ __forceinline__ void ldmx4(uint32_t r[4], uint32_t a) {
    asm volatile("ldmatrix.sync.aligned.m8n8.x4.shared.b16 {%0,%1,%2,%3}, [%4];"
                 : "=r"(r[0]), "=r"(r[1]), "=r"(r[2]), "=r"(r[3]) : "r"(a));
}
__device__ __forceinline__ void ldmx2(uint32_t r[2], uint32_t a) {
    asm volatile("ldmatrix.sync.aligned.m8n8.x2.shared.b16 {%0,%1}, [%2];"
                 : "=r"(r[0]), "=r"(r[1]) : "r"(a));
}
__device__ __forceinline__ void mma_bf16(float d[4], const uint32_t a[4],
                                         const uint32_t b[2]) {
    asm volatile("mma.sync.aligned.m16n8k16.row.col.f32.bf16.bf16.f32 "
                 "{%0,%1,%2,%3},{%4,%5,%6,%7},{%8,%9},{%0,%1,%2,%3};"
                 : "+f"(d[0]), "+f"(d[1]), "+f"(d[2]), "+f"(d[3])
                 : "r"(a[0]), "r"(a[1]), "r"(a[2]), "r"(a[3]),
                   "r"(b[0]), "r"(b[1]));
}
#define CP_ASYNC(dst, src) \
    asm volatile("cp.async.cg.shared.global [%0], [%1], 16;" :: "r"(dst), "l"(src))
#define CP_COMMIT() asm volatile("cp.async.commit_group;" ::: "memory")

// ================= k1: norm_scale = cond @ w_cond.T + 1 =================
__global__ void k_cond(const float* __restrict__ cond,
                       const float* __restrict__ w_cond) {
    int w    = (blockIdx.x * blockDim.x + threadIdx.x) >> 5;
    int lane = threadIdx.x & 31;
    if (w >= 2 * DM) return;
    int n = w >> 9, c = w & 511;
    const float* cp = cond + n * CND;
    const float* wp = w_cond + c * CND;
    float s = 0.f;
    #pragma unroll 4
    for (int k = lane; k < CND; k += 32) s += cp[k] * wp[k];
    #pragma unroll
    for (int o = 16; o; o >>= 1) s += __shfl_xor_sync(~0u, s, o);
    if (!lane) g_nscale[w] = s + 1.0f;
}

// ===== k2: fused per-token RMS + scale + bf16 hi/lo convert of A =====
__global__ void k_prep_a(const float* __restrict__ x) {
    int wid = threadIdx.x >> 5, lane = threadIdx.x & 31;
    int row = blockIdx.x * 8 + wid;
    const float4* xp = (const float4*)(x + (size_t)row * DM);
    float4 vv[4];
    float s = 0.f;
    #pragma unroll
    for (int i = 0; i < 4; i++) {
        vv[i] = xp[i * 32 + lane];
        s += vv[i].x * vv[i].x + vv[i].y * vv[i].y +
             vv[i].z * vv[i].z + vv[i].w * vv[i].w;
    }
    #pragma unroll
    for (int o = 16; o; o >>= 1) s += __shfl_xor_sync(~0u, s, o);
    float rstd = rsqrtf(s * (1.0f / DM) + 1e-6f);
    const float* nsc = g_nscale + (row >> 10) * DM;
    #pragma unroll
    for (int i = 0; i < 4; i++) {
        int c0 = (i * 32 + lane) * 4;
        float a = vv[i].x * rstd * nsc[c0];
        float b = vv[i].y * rstd * nsc[c0 + 1];
        float c = vv[i].z * rstd * nsc[c0 + 2];
        float d = vv[i].w * rstd * nsc[c0 + 3];
        uint32_t h0, l0, h1, l1;
        split2(a, b, h0, l0);
        split2(c, d, h1, l1);
        *(uint2*)(g_ah + (size_t)row * DM + c0) = make_uint2(h0, h1);
        *(uint2*)(g_al + (size_t)row * DM + c0) = make_uint2(l0, l1);
    }
}

// ===== generic fp32 -> bf16 hi/lo converter. DSTA=0 -> g_bh/g_bl, 1 -> g_ah/g_al
template <int DSTA>
__global__ void k_cvt(const float* __restrict__ src, int total) {
    int idx = (blockIdx.x * 256 + threadIdx.x) * 4;
    if (idx >= total) return;
    const float* s = src ? src : (const float*)g_o;
    float4 v = *(const float4*)(s + idx);
    uint32_t h0, l0, h1, l1;
    split2(v.x, v.y, h0, l0);
    split2(v.z, v.w, h1, l1);
    __nv_bfloat16* dh = DSTA ? g_ah : g_bh;
    __nv_bfloat16* dl = DSTA ? g_al : g_bl;
    *(uint2*)(dh + idx) = make_uint2(h0, h1);
    *(uint2*)(dl + idx) = make_uint2(l0, l1);
}

// ====== bf16 3-term split GEMM via mma.sync, cp.async 4-stage pipeline ======
// MODE 0: C = A@Wqkv^T, scatter into g_q/g_k/g_v head-major.
// MODE 1: C = A@Wout^T + skip -> outp.
// BM=BN=128, BK=32. Stage = 4 planes (Ah,Al,Bh,Bl) x 128x32 bf16 = 32KB.
#define STG_SZ   32768
#define PLN_SZ   8192
#define MM_SMEM  (4 * STG_SZ)

template <int MODE>
__global__ __launch_bounds__(256) void k_mm(const float* __restrict__ skip,
                                            float* __restrict__ outp) {
    extern __shared__ char smem[];
    const uint32_t sb = smem_u32(smem);
    const int t = threadIdx.x, lane = t & 31, wid = t >> 5;
    const int m0 = blockIdx.y * 128, n0 = blockIdx.x * 128;
    const int mbase = (wid >> 2) * 64, nbase = (wid & 3) * 32;
    const int qy = lane >> 2, t4 = lane & 3;

    float acc[4][4][4];
    #pragma unroll
    for (int i = 0; i < 4; i++)
        #pragma unroll
        for (int j = 0; j < 4; j++)
            #pragma unroll
            for (int r = 0; r < 4; r++) acc[i][j][r] = 0.f;

    auto issue = [&](int s) {
        if (s < 16) {
            int k0 = s * 32;
            uint32_t stb = sb + (s & 3) * STG_SZ;
            #pragma unroll
            for (int i = 0; i < 8; i++) {
                int plane = i >> 1;
                int rc = (i & 1) * 256 + t;
                int row = rc >> 2, c = rc & 3;
                int phys = (c + (row >> 1)) & 3;
                uint32_t dst = stb + plane * PLN_SZ + row * 64 + phys * 16;
                const __nv_bfloat16* g;
                if (plane == 0)      g = g_ah + (size_t)(m0 + row) * DM + k0 + c * 8;
                else if (plane == 1) g = g_al + (size_t)(m0 + row) * DM + k0 + c * 8;
                else if (plane == 2) g = g_bh + (size_t)(n0 + row) * DM + k0 + c * 8;
                else                 g = g_bl + (size_t)(n0 + row) * DM + k0 + c * 8;
                CP_ASYNC(dst, g);
            }
        }
        CP_COMMIT();
    };

    issue(0); issue(1); issue(2);

    for (int it = 0; it < 16; ++it) {
        if (it < 13) asm volatile("cp.async.wait_group 2;" ::: "memory");
        else         asm volatile("cp.async.wait_group 0;" ::: "memory");
        __syncthreads();
        uint32_t stb = sb + (it & 3) * STG_SZ;
        #pragma unroll
        for (int kk = 0; kk < 2; ++kk) {
            uint32_t ah[4][4], al[4][4], bh[4][2], bl[4][2];
            #pragma unroll
            for (int mt = 0; mt < 4; ++mt) {
                int row = mbase + mt * 16 + (lane & 15);
                int c = kk * 2 + (lane >> 4);
                int phys = (c + (row >> 1)) & 3;
                uint32_t ad = stb + row * 64 + phys * 16;
                ldmx4(ah[mt], ad);
                ldmx4(al[mt], ad + PLN_SZ);
            }
            #pragma unroll
            for (int nt = 0; nt < 4; ++nt) {
                int row = nbase + nt * 8 + (lane & 7);
                int c = kk * 2 + ((lane >> 3) & 1);
                int phys = (c + (row >> 1)) & 3;
                uint32_t ad = stb + 2 * PLN_SZ + row * 64 + phys * 16;
                ldmx2(bh[nt], ad);
                ldmx2(bl[nt], ad + PLN_SZ);
            }
            #pragma unroll
            for (int mt = 0; mt < 4; ++mt)
                #pragma unroll
                for (int nt = 0; nt < 4; ++nt) mma_bf16(acc[mt][nt], ah[mt], bh[nt]);
            #pragma unroll
            for (int mt = 0; mt < 4; ++mt)
                #pragma unroll
                for (int nt = 0; nt < 4; ++nt) mma_bf16(acc[mt][nt], al[mt], bh[nt]);
            #pragma unroll
            for (int mt = 0; mt < 4; ++mt)
                #pragma unroll
                for (int nt = 0; nt < 4; ++nt) mma_bf16(acc[mt][nt], ah[mt], bl[nt]);
        }
        issue(it + 3);
    }

    // ---- epilogue ----
    const int nb = m0 >> 10;
    #pragma unroll
    for (int mt = 0; mt < 4; ++mt) {
        int r0 = m0 + mbase + mt * 16 + qy;
        #pragma unroll
        for (int nt = 0; nt < 4; ++nt) {
            int col = n0 + nbase + nt * 8 + 2 * t4;
            if (MODE == 0) {
                int part = col >> 9;
                int head = (col >> 6) & 7;
                int d0   = col & 63;
                int ij0  = r0 & 1023, ij1 = (r0 + 8) & 1023;
                float* dst = ((part == 0) ? g_q : (part == 1) ? g_k : g_v)
                             + ((size_t)(nb * NH + head) * 1024) * DH + d0;
                float2 v0 = {acc[mt][nt][0], acc[mt][nt][1]};
                float2 v1 = {acc[mt][nt][2], acc[mt][nt][3]};
                *(float2*)(dst + (size_t)ij0 * DH) = v0;
                *(float2*)(dst + (size_t)ij1 * DH) = v1;
            } else {
                float2 s0 = *(const float2*)(skip + (size_t)r0 * DM + col);
                float2 s1 = *(const float2*)(skip + (size_t)(r0 + 8) * DM + col);
                float2 v0 = {acc[mt][nt][0] + s0.x, acc[mt][nt][1] + s0.y};
                float2 v1 = {acc[mt][nt][2] + s1.x, acc[mt][nt][3] + s1.y};
                *(float2*)(outp + (size_t)r0 * DM + col)       = v0;
                *(float2*)(outp + (size_t)(r0 + 8) * DM + col) = v1;
            }
        }
    }
}

// ====== k4: per-head L2 norm + RoPE ======
__global__ void k_rope(const float* __restrict__ pos,
                       const float* __restrict__ scale) {
    int w    = (blockIdx.x * blockDim.x + threadIdx.x) >> 5;
    int lane = threadIdx.x & 31;
    const int total = 2 * NH * 1024;
    if (w >= 2 * total) return;
    float* buf = (w < total) ? g_q : g_k;
    int v  = (w < total) ? w : w - total;
    int n  = v >> 13;
    int h  = (v >> 10) & 7;
    int ij = v & 1023;
    float* p = buf + (size_t)v * DH;

    float a = p[lane];
    float b = p[lane + 32];
    float s = a * a + b * b;
    #pragma unroll
    for (int o = 16; o; o >>= 1) s += __shfl_xor_sync(~0u, s, o);
    float fac = sqrtf(scale[h]) * rsqrtf(s + 1e-6f);
    a *= fac;
    b *= fac;

    int m = lane & 15;
    float freq = 3.14159265358979f * __expf((float)(m * 8 + h) * (2.302585092994046f / 128.0f));
    float th = pos[n * 1024 + ij] * freq;
    float sn, cs;
    __sincosf(th, &sn, &cs);
    float partner = __shfl_xor_sync(~0u, a, 16);
    float na = (lane < 16) ? (a * cs - partner * sn) : (a * cs + partner * sn);
    p[lane]      = na;
    p[lane + 32] = b;
}

// ====== k5: 7x7 neighborhood attention (fp32) ======
__global__ __launch_bounds__(256) void k_attn() {
    extern __shared__ float sm[];
    float* Ks = sm;
    float* Vs = sm + 196 * PAD;
    int b    = blockIdx.x;
    int tile = b & 15;
    int h    = (b >> 4) & 7;
    int n    = b >> 7;
    int i0 = (tile >> 2) * 8, j0 = (tile & 3) * 8;
    int rbase = min(max(i0 - 3, 0), 18);
    int cbase = min(max(j0 - 3, 0), 18);

    const float* kb = g_k + (size_t)((n * NH + h) * 1024) * DH;
    const float* vb = g_v + (size_t)((n * NH + h) * 1024) * DH;

    for (int idx = threadIdx.x; idx < 196 * 16; idx += 256) {
        int px = idx >> 4, u = idx & 15;
        int r = px / 14, cc = px - r * 14;
        int g = ((rbase + r) * 32 + cbase + cc) * 16 + u;
        ((float4*)(Ks + px * PAD))[u] = ((const float4*)kb)[g];
        ((float4*)(Vs + px * PAD))[u] = ((const float4*)vb)[g];
    }
    __syncthreads();

    int p = threadIdx.x >> 2, s = threadIdx.x & 3;
    int gi = i0 + (p >> 3), gj = j0 + (p & 7);
    int si = min(max(gi - 3, 0), 25) - rbase;
    int sj = min(max(gj - 3, 0), 25) - cbase;

    const float* qp = g_q + ((size_t)((n * NH + h) * 1024) + gi * 32 + gj) * DH + s * 16;
    float4 q0 = ((const float4*)qp)[0];
    float4 q1 = ((const float4*)qp)[1];
    float4 q2 = ((const float4*)qp)[2];
    float4 q3 = ((const float4*)qp)[3];

    float logit[49];
    #pragma unroll
    for (int a = 0; a < 7; a++) {
        #pragma unroll
        for (int bb = 0; bb < 7; bb++) {
            const float* kp = Ks + ((si + a) * 14 + sj + bb) * PAD + s * 16;
            float4 c0 = ((const float4*)kp)[0];
            float4 c1 = ((const float4*)kp)[1];
            float4 c2 = ((const float4*)kp)[2];
            float4 c3 = ((const float4*)kp)[3];
            float d = q0.x * c0.x + q0.y * c0.y + q0.z * c0.z + q0.w * c0.w
                    + q1.x * c1.x + q1.y * c1.y + q1.z * c1.z + q1.w * c1.w
                    + q2.x * c2.x + q2.y * c2.y + q2.z * c2.z + q2.w * c2.w
                    + q3.x * c3.x + q3.y * c3.y + q3.z * c3.z + q3.w * c3.w;
            d += __shfl_xor_sync(~0u, d, 1);
            d += __shfl_xor_sync(~0u, d, 2);
            logit[a * 7 + bb] = d;
        }
    }

    float mx = -1e30f;
    #pragma unroll
    for (int i = 0; i < 49; i++) mx = fmaxf(mx, logit[i]);
    float sum = 0.f;
    #pragma unroll
    for (int i = 0; i < 49; i++) {
        float e = __expf(logit[i] - mx);
        logit[i] = e;
        sum += e;
    }
    float inv = 1.0f / sum;

    float acc[16];
    #pragma unroll
    for (int j = 0; j < 16; j++) acc[j] = 0.f;
    #pragma unroll
    for (int a = 0; a < 7; a++) {
        #pragma unroll
        for (int bb = 0; bb < 7; bb++) {
            float wgt = logit[a * 7 + bb];
            const float* vp = Vs + ((si + a) * 14 + sj + bb) * PAD + s * 16;
            #pragma unroll
            for (int j = 0; j < 16; j++) acc[j] += wgt * vp[j];
        }
    }

    float* op = g_o + (size_t)(n * 1024 + gi * 32 + gj) * DM + h * DH + s * 16;
    #pragma unroll
    for (int u = 0; u < 4; u++) {
        float4 o4 = {acc[u * 4 + 0] * inv, acc[u * 4 + 1] * inv,
                     acc[u * 4 + 2] * inv, acc[u * 4 + 3] * inv};
        ((float4*)op)[u] = o4;
    }
}

// =========================== launch ===========================
extern "C" void kernel_launch(void* const* d_in, const int* in_sizes, int n_in,
                              void* d_out, int out_size) {
    const float* x      = (const float*)d_in[0];
    const float* pos    = (const float*)d_in[1];
    const float* cond   = (const float*)d_in[2];
    const float* w_cond = (const float*)d_in[3];
    const float* w_qkv  = (const float*)d_in[4];
    const float* scale  = (const float*)d_in[5];
    const float* w_out  = (const float*)d_in[6];
    float* out = (float*)d_out;

    const int attn_smem = 2 * 196 * PAD * 4;
    cudaFuncSetAttribute(k_attn, cudaFuncAttributeMaxDynamicSharedMemorySize,
                         attn_smem);
    cudaFuncSetAttribute(k_mm<0>, cudaFuncAttributeMaxDynamicSharedMemorySize,
                         MM_SMEM);
    cudaFuncSetAttribute(k_mm<1>, cudaFuncAttributeMaxDynamicSharedMemorySize,
                         MM_SMEM);

    k_cond<<<128, 256>>>(cond, w_cond);
    k_prep_a<<<256, 256>>>(x);
    k_cvt<0><<<768, 256>>>(w_qkv, 3 * DM * DM);
    k_mm<0><<<dim3(12, 16), 256, MM_SMEM>>>(nullptr, nullptr);
    k_rope<<<4096, 256>>>(pos, scale);
    k_attn<<<256, 256, attn_smem>>>();
    k_cvt<1><<<1024, 256>>>(nullptr, NTOK * DM);       // g_o -> g_ah/g_al
    k_cvt<0><<<256, 256>>>(w_out, DM * DM);            // w_out -> g_bh/g_bl
    k_mm<1><<<dim3(4, 16), 256, MM_SMEM>>>(x, out);
}

// round 8
// speedup vs baseline: 2.0307x; 1.0817x over previous
#include <cuda_runtime.h>
#include <cuda_bf16.h>
#include <math.h>
#include <stdint.h>

#define NTOK 2048
#define DM   512
#define NH   8
#define DH   64
#define CND  768
#define PAD  68

// -------- scratch (device globals; no allocation allowed) --------
__device__ float g_nscale[2 * DM];
__device__ __align__(16) float g_q[2 * NH * 1024 * DH];
__device__ __align__(16) float g_k[2 * NH * 1024 * DH];
__device__ __align__(16) float g_v[2 * NH * 1024 * DH];
// bf16 hi/lo planes
__device__ __align__(16) __nv_bfloat16 g_ah[NTOK * DM];
__device__ __align__(16) __nv_bfloat16 g_al[NTOK * DM];
__device__ __align__(16) __nv_bfloat16 g_bh[3 * DM * DM];
__device__ __align__(16) __nv_bfloat16 g_bl[3 * DM * DM];

// ---------------- helpers ----------------
__device__ __forceinline__ uint32_t smem_u32(const void* p) {
    uint32_t a;
    asm("{ .reg .u64 t; cvta.to.shared.u64 t, %1; cvt.u32.u64 %0, t; }"
        : "=r"(a) : "l"(p));
    return a;
}
__device__ __forceinline__ uint32_t pack2(__nv_bfloat16 a, __nv_bfloat16 b) {
    __nv_bfloat162 t = __halves2bfloat162(a, b);
    return *reinterpret_cast<uint32_t*>(&t);
}
__device__ __forceinline__ void split2(float a, float b, uint32_t& h, uint32_t& l) {
    __nv_bfloat16 ha = __float2bfloat16_rn(a), hb = __float2bfloat16_rn(b);
    h = pack2(ha, hb);
    l = pack2(__float2bfloat16_rn(a - __bfloat162float(ha)),
              __float2bfloat16_rn(b - __bfloat162float(hb)));
}
__device__ __forceinline__ void ldmx4(uint32_t r[4], uint32_t a) {
    asm volatile("ldmatrix.sync.aligned.m8n8.x4.shared.b16 {%0,%1,%2,%3}, [%4];"
                 : "=r"(r[0]), "=r"(r[1]), "=r"(r[2]), "=r"(r[3]) : "r"(a));
}
__device__ __forceinline__ void ldmx2(uint32_t r[2], uint32_t a) {
    asm volatile("ldmatrix.sync.aligned.m8n8.x2.shared.b16 {%0,%1}, [%2];"
                 : "=r"(r[0]), "=r"(r[1]) : "r"(a));
}
__device__ __forceinline__ void mma_bf16(float d[4], const uint32_t a[4],
                                         const uint32_t b[2]) {
    asm volatile("mma.sync.aligned.m16n8k16.row.col.f32.bf16.bf16.f32 "
                 "{%0,%1,%2,%3},{%4,%5,%6,%7},{%8,%9},{%0,%1,%2,%3};"
                 : "+f"(d[0]), "+f"(d[1]), "+f"(d[2]), "+f"(d[3])
                 : "r"(a[0]), "r"(a[1]), "r"(a[2]), "r"(a[3]),
                   "r"(b[0]), "r"(b[1]));
}
#define CP_ASYNC(dst, src) \
    asm volatile("cp.async.cg.shared.global [%0], [%1], 16;" :: "r"(dst), "l"(src))
#define CP_COMMIT() asm volatile("cp.async.commit_group;" ::: "memory")

// ================= k1: norm_scale = cond @ w_cond.T + 1 =================
__global__ void k_cond(const float* __restrict__ cond,
                       const float* __restrict__ w_cond) {
    int w    = (blockIdx.x * blockDim.x + threadIdx.x) >> 5;
    int lane = threadIdx.x & 31;
    if (w >= 2 * DM) return;
    int n = w >> 9, c = w & 511;
    const float* cp = cond + n * CND;
    const float* wp = w_cond + c * CND;
    float s = 0.f;
    #pragma unroll 4
    for (int k = lane; k < CND; k += 32) s += cp[k] * wp[k];
    #pragma unroll
    for (int o = 16; o; o >>= 1) s += __shfl_xor_sync(~0u, s, o);
    if (!lane) g_nscale[w] = s + 1.0f;
}

// ===== k2: fused per-token RMS + scale + bf16 hi/lo convert of A =====
__global__ void k_prep_a(const float* __restrict__ x) {
    int wid = threadIdx.x >> 5, lane = threadIdx.x & 31;
    int row = blockIdx.x * 8 + wid;
    const float4* xp = (const float4*)(x + (size_t)row * DM);
    float4 vv[4];
    float s = 0.f;
    #pragma unroll
    for (int i = 0; i < 4; i++) {
        vv[i] = xp[i * 32 + lane];
        s += vv[i].x * vv[i].x + vv[i].y * vv[i].y +
             vv[i].z * vv[i].z + vv[i].w * vv[i].w;
    }
    #pragma unroll
    for (int o = 16; o; o >>= 1) s += __shfl_xor_sync(~0u, s, o);
    float rstd = rsqrtf(s * (1.0f / DM) + 1e-6f);
    const float* nsc = g_nscale + (row >> 10) * DM;
    #pragma unroll
    for (int i = 0; i < 4; i++) {
        int c0 = (i * 32 + lane) * 4;
        float a = vv[i].x * rstd * nsc[c0];
        float b = vv[i].y * rstd * nsc[c0 + 1];
        float c = vv[i].z * rstd * nsc[c0 + 2];
        float d = vv[i].w * rstd * nsc[c0 + 3];
        uint32_t h0, l0, h1, l1;
        split2(a, b, h0, l0);
        split2(c, d, h1, l1);
        *(uint2*)(g_ah + (size_t)row * DM + c0) = make_uint2(h0, h1);
        *(uint2*)(g_al + (size_t)row * DM + c0) = make_uint2(l0, l1);
    }
}

// ===== weight fp32 -> bf16 hi/lo converter (into g_bh/g_bl) =====
__global__ void k_cvt_b(const float* __restrict__ src, int total) {
    int idx = (blockIdx.x * 256 + threadIdx.x) * 4;
    if (idx >= total) return;
    float4 v = *(const float4*)(src + idx);
    uint32_t h0, l0, h1, l1;
    split2(v.x, v.y, h0, l0);
    split2(v.z, v.w, h1, l1);
    *(uint2*)(g_bh + idx) = make_uint2(h0, h1);
    *(uint2*)(g_bl + idx) = make_uint2(l0, l1);
}

// ====== bf16 3-term split GEMM via mma.sync, cp.async 3-stage pipeline ======
// MODE 0: C = A@Wqkv^T, scatter into g_q/g_k/g_v head-major.
// MODE 1: C = A@Wout^T + skip -> outp.
// BM=BN=128, BK=32. Stage = 4 planes (Ah,Al,Bh,Bl) x 128x32 bf16 = 32KB.
#define STG_SZ   32768
#define PLN_SZ   8192
#define MM_SMEM  (3 * STG_SZ)

template <int MODE>
__global__ __launch_bounds__(256, 2) void k_mm(const float* __restrict__ skip,
                                               float* __restrict__ outp) {
    extern __shared__ char smem[];
    const uint32_t sb = smem_u32(smem);
    const int t = threadIdx.x, lane = t & 31, wid = t >> 5;
    const int m0 = blockIdx.y * 128, n0 = blockIdx.x * 128;
    const int mbase = (wid >> 2) * 64, nbase = (wid & 3) * 32;
    const int qy = lane >> 2, t4 = lane & 3;

    float acc[4][4][4];
    #pragma unroll
    for (int i = 0; i < 4; i++)
        #pragma unroll
        for (int j = 0; j < 4; j++)
            #pragma unroll
            for (int r = 0; r < 4; r++) acc[i][j][r] = 0.f;

    auto issue = [&](int s) {
        if (s < 16) {
            int k0 = s * 32;
            uint32_t stb = sb + (s % 3) * STG_SZ;
            #pragma unroll
            for (int i = 0; i < 8; i++) {
                int plane = i >> 1;
                int rc = (i & 1) * 256 + t;
                int row = rc >> 2, c = rc & 3;
                int phys = (c + (row >> 1)) & 3;
                uint32_t dst = stb + plane * PLN_SZ + row * 64 + phys * 16;
                const __nv_bfloat16* g;
                if (plane == 0)      g = g_ah + (size_t)(m0 + row) * DM + k0 + c * 8;
                else if (plane == 1) g = g_al + (size_t)(m0 + row) * DM + k0 + c * 8;
                else if (plane == 2) g = g_bh + (size_t)(n0 + row) * DM + k0 + c * 8;
                else                 g = g_bl + (size_t)(n0 + row) * DM + k0 + c * 8;
                CP_ASYNC(dst, g);
            }
        }
        CP_COMMIT();
    };

    issue(0); issue(1);

    for (int it = 0; it < 16; ++it) {
        if (it < 15) asm volatile("cp.async.wait_group 1;" ::: "memory");
        else         asm volatile("cp.async.wait_group 0;" ::: "memory");
        __syncthreads();
        uint32_t stb = sb + (it % 3) * STG_SZ;
        #pragma unroll
        for (int kk = 0; kk < 2; ++kk) {
            uint32_t ah[4][4], al[4][4], bh[4][2], bl[4][2];
            #pragma unroll
            for (int mt = 0; mt < 4; ++mt) {
                int row = mbase + mt * 16 + (lane & 15);
                int c = kk * 2 + (lane >> 4);
                int phys = (c + (row >> 1)) & 3;
                uint32_t ad = stb + row * 64 + phys * 16;
                ldmx4(ah[mt], ad);
                ldmx4(al[mt], ad + PLN_SZ);
            }
            #pragma unroll
            for (int nt = 0; nt < 4; ++nt) {
                int row = nbase + nt * 8 + (lane & 7);
                int c = kk * 2 + ((lane >> 3) & 1);
                int phys = (c + (row >> 1)) & 3;
                uint32_t ad = stb + 2 * PLN_SZ + row * 64 + phys * 16;
                ldmx2(bh[nt], ad);
                ldmx2(bl[nt], ad + PLN_SZ);
            }
            #pragma unroll
            for (int mt = 0; mt < 4; ++mt)
                #pragma unroll
                for (int nt = 0; nt < 4; ++nt) mma_bf16(acc[mt][nt], ah[mt], bh[nt]);
            #pragma unroll
            for (int mt = 0; mt < 4; ++mt)
                #pragma unroll
                for (int nt = 0; nt < 4; ++nt) mma_bf16(acc[mt][nt], al[mt], bh[nt]);
            #pragma unroll
            for (int mt = 0; mt < 4; ++mt)
                #pragma unroll
                for (int nt = 0; nt < 4; ++nt) mma_bf16(acc[mt][nt], ah[mt], bl[nt]);
        }
        issue(it + 2);
    }

    // ---- epilogue ----
    const int nb = m0 >> 10;
    #pragma unroll
    for (int mt = 0; mt < 4; ++mt) {
        int r0 = m0 + mbase + mt * 16 + qy;
        #pragma unroll
        for (int nt = 0; nt < 4; ++nt) {
            int col = n0 + nbase + nt * 8 + 2 * t4;
            if (MODE == 0) {
                int part = col >> 9;
                int head = (col >> 6) & 7;
                int d0   = col & 63;
                int ij0  = r0 & 1023, ij1 = (r0 + 8) & 1023;
                float* dst = ((part == 0) ? g_q : (part == 1) ? g_k : g_v)
                             + ((size_t)(nb * NH + head) * 1024) * DH + d0;
                float2 v0 = {acc[mt][nt][0], acc[mt][nt][1]};
                float2 v1 = {acc[mt][nt][2], acc[mt][nt][3]};
                *(float2*)(dst + (size_t)ij0 * DH) = v0;
                *(float2*)(dst + (size_t)ij1 * DH) = v1;
            } else {
                float2 s0 = *(const float2*)(skip + (size_t)r0 * DM + col);
                float2 s1 = *(const float2*)(skip + (size_t)(r0 + 8) * DM + col);
                float2 v0 = {acc[mt][nt][0] + s0.x, acc[mt][nt][1] + s0.y};
                float2 v1 = {acc[mt][nt][2] + s1.x, acc[mt][nt][3] + s1.y};
                *(float2*)(outp + (size_t)r0 * DM + col)       = v0;
                *(float2*)(outp + (size_t)(r0 + 8) * DM + col) = v1;
            }
        }
    }
}

// ====== k4: per-head L2 norm + RoPE ======
__global__ void k_rope(const float* __restrict__ pos,
                       const float* __restrict__ scale) {
    int w    = (blockIdx.x * blockDim.x + threadIdx.x) >> 5;
    int lane = threadIdx.x & 31;
    const int total = 2 * NH * 1024;
    if (w >= 2 * total) return;
    float* buf = (w < total) ? g_q : g_k;
    int v  = (w < total) ? w : w - total;
    int n  = v >> 13;
    int h  = (v >> 10) & 7;
    int ij = v & 1023;
    float* p = buf + (size_t)v * DH;

    float a = p[lane];
    float b = p[lane + 32];
    float s = a * a + b * b;
    #pragma unroll
    for (int o = 16; o; o >>= 1) s += __shfl_xor_sync(~0u, s, o);
    float fac = sqrtf(scale[h]) * rsqrtf(s + 1e-6f);
    a *= fac;
    b *= fac;

    int m = lane & 15;
    float freq = 3.14159265358979f * __expf((float)(m * 8 + h) * (2.302585092994046f / 128.0f));
    float th = pos[n * 1024 + ij] * freq;
    float sn, cs;
    __sincosf(th, &sn, &cs);
    float partner = __shfl_xor_sync(~0u, a, 16);
    float na = (lane < 16) ? (a * cs - partner * sn) : (a * cs + partner * sn);
    p[lane]      = na;
    p[lane + 32] = b;
}

// ====== k5: 7x7 neighborhood attention (fp32, writes bf16 hi/lo planes) ======
__global__ __launch_bounds__(256, 2) void k_attn() {
    extern __shared__ float sm[];
    float* Ks = sm;
    float* Vs = sm + 196 * PAD;
    int b    = blockIdx.x;
    int tile = b & 15;
    int h    = (b >> 4) & 7;
    int n    = b >> 7;
    int i0 = (tile >> 2) * 8, j0 = (tile & 3) * 8;
    int rbase = min(max(i0 - 3, 0), 18);
    int cbase = min(max(j0 - 3, 0), 18);

    const float* kb = g_k + (size_t)((n * NH + h) * 1024) * DH;
    const float* vb = g_v + (size_t)((n * NH + h) * 1024) * DH;

    for (int idx = threadIdx.x; idx < 196 * 16; idx += 256) {
        int px = idx >> 4, u = idx & 15;
        int r = px / 14, cc = px - r * 14;
        int g = ((rbase + r) * 32 + cbase + cc) * 16 + u;
        ((float4*)(Ks + px * PAD))[u] = ((const float4*)kb)[g];
        ((float4*)(Vs + px * PAD))[u] = ((const float4*)vb)[g];
    }
    __syncthreads();

    int p = threadIdx.x >> 2, s = threadIdx.x & 3;
    int gi = i0 + (p >> 3), gj = j0 + (p & 7);
    int si = min(max(gi - 3, 0), 25) - rbase;
    int sj = min(max(gj - 3, 0), 25) - cbase;

    const float* qp = g_q + ((size_t)((n * NH + h) * 1024) + gi * 32 + gj) * DH + s * 16;
    float4 q0 = ((const float4*)qp)[0];
    float4 q1 = ((const float4*)qp)[1];
    float4 q2 = ((const float4*)qp)[2];
    float4 q3 = ((const float4*)qp)[3];

    float logit[49];
    #pragma unroll
    for (int a = 0; a < 7; a++) {
        #pragma unroll
        for (int bb = 0; bb < 7; bb++) {
            const float* kp = Ks + ((si + a) * 14 + sj + bb) * PAD + s * 16;
            float4 c0 = ((const float4*)kp)[0];
            float4 c1 = ((const float4*)kp)[1];
            float4 c2 = ((const float4*)kp)[2];
            float4 c3 = ((const float4*)kp)[3];
            float d = q0.x * c0.x + q0.y * c0.y + q0.z * c0.z + q0.w * c0.w
                    + q1.x * c1.x + q1.y * c1.y + q1.z * c1.z + q1.w * c1.w
                    + q2.x * c2.x + q2.y * c2.y + q2.z * c2.z + q2.w * c2.w
                    + q3.x * c3.x + q3.y * c3.y + q3.z * c3.z + q3.w * c3.w;
            d += __shfl_xor_sync(~0u, d, 1);
            d += __shfl_xor_sync(~0u, d, 2);
            logit[a * 7 + bb] = d;
        }
    }

    float mx = -1e30f;
    #pragma unroll
    for (int i = 0; i < 49; i++) mx = fmaxf(mx, logit[i]);
    float sum = 0.f;
    #pragma unroll
    for (int i = 0; i < 49; i++) {
        float e = __expf(logit[i] - mx);
        logit[i] = e;
        sum += e;
    }
    float inv = 1.0f / sum;

    float acc[16];
    #pragma unroll
    for (int j = 0; j < 16; j++) acc[j] = 0.f;
    #pragma unroll
    for (int a = 0; a < 7; a++) {
        #pragma unroll
        for (int bb = 0; bb < 7; bb++) {
            float wgt = logit[a * 7 + bb];
            const float* vp = Vs + ((si + a) * 14 + sj + bb) * PAD + s * 16;
            #pragma unroll
            for (int j = 0; j < 16; j++) acc[j] += wgt * vp[j];
        }
    }

    // write attention output directly as bf16 hi/lo planes (A of out GEMM)
    size_t off = (size_t)(n * 1024 + gi * 32 + gj) * DM + h * DH + s * 16;
    uint32_t hw[8], lw[8];
    #pragma unroll
    for (int u = 0; u < 8; ++u)
        split2(acc[2 * u] * inv, acc[2 * u + 1] * inv, hw[u], lw[u]);
    *(uint4*)(g_ah + off)     = make_uint4(hw[0], hw[1], hw[2], hw[3]);
    *(uint4*)(g_ah + off + 8) = make_uint4(hw[4], hw[5], hw[6], hw[7]);
    *(uint4*)(g_al + off)     = make_uint4(lw[0], lw[1], lw[2], lw[3]);
    *(uint4*)(g_al + off + 8) = make_uint4(lw[4], lw[5], lw[6], lw[7]);
}

// =========================== launch ===========================
extern "C" void kernel_launch(void* const* d_in, const int* in_sizes, int n_in,
                              void* d_out, int out_size) {
    const float* x      = (const float*)d_in[0];
    const float* pos    = (const float*)d_in[1];
    const float* cond   = (const float*)d_in[2];
    const float* w_cond = (const float*)d_in[3];
    const float* w_qkv  = (const float*)d_in[4];
    const float* scale  = (const float*)d_in[5];
    const float* w_out  = (const float*)d_in[6];
    float* out = (float*)d_out;

    const int attn_smem = 2 * 196 * PAD * 4;
    cudaFuncSetAttribute(k_attn, cudaFuncAttributeMaxDynamicSharedMemorySize,
                         attn_smem);
    cudaFuncSetAttribute(k_mm<0>, cudaFuncAttributeMaxDynamicSharedMemorySize,
                         MM_SMEM);
    cudaFuncSetAttribute(k_mm<1>, cudaFuncAttributeMaxDynamicSharedMemorySize,
                         MM_SMEM);

    k_cond<<<128, 256>>>(cond, w_cond);
    k_prep_a<<<256, 256>>>(x);
    k_cvt_b<<<768, 256>>>(w_qkv, 3 * DM * DM);
    k_mm<0><<<dim3(12, 16), 256, MM_SMEM>>>(nullptr, nullptr);
    k_rope<<<4096, 256>>>(pos, scale);
    k_attn<<<256, 256, attn_smem>>>();
    k_cvt_b<<<256, 256>>>(w_out, DM * DM);   // w_out -> g_bh/g_bl
    k_mm<1><<<dim3(4, 16), 256, MM_SMEM>>>(x, out);
}

// round 10
// speedup vs baseline: 2.2108x; 1.0887x over previous
#include <cuda_runtime.h>
#include <cuda_bf16.h>
#include <math.h>
#include <stdint.h>

#define NTOK 2048
#define DM   512
#define NH   8
#define DH   64
#define CND  768
#define PAD  68

// -------- scratch (device globals; no allocation allowed) --------
__device__ float g_nscale[2 * DM];
__device__ __align__(16) float g_q[2 * NH * 1024 * DH];
__device__ __align__(16) float g_k[2 * NH * 1024 * DH];
__device__ __align__(16) float g_v[2 * NH * 1024 * DH];
// bf16 hi/lo planes
__device__ __align__(16) __nv_bfloat16 g_ah[NTOK * DM];
__device__ __align__(16) __nv_bfloat16 g_al[NTOK * DM];
__device__ __align__(16) __nv_bfloat16 g_bh[3 * DM * DM];
__device__ __align__(16) __nv_bfloat16 g_bl[3 * DM * DM];

// ---------------- helpers ----------------
__device__ __forceinline__ uint32_t smem_u32(const void* p) {
    uint32_t a;
    asm("{ .reg .u64 t; cvta.to.shared.u64 t, %1; cvt.u32.u64 %0, t; }"
        : "=r"(a) : "l"(p));
    return a;
}
__device__ __forceinline__ uint32_t pack2(__nv_bfloat16 a, __nv_bfloat16 b) {
    __nv_bfloat162 t = __halves2bfloat162(a, b);
    return *reinterpret_cast<uint32_t*>(&t);
}
__device__ __forceinline__ void split2(float a, float b, uint32_t& h, uint32_t& l) {
    __nv_bfloat16 ha = __float2bfloat16_rn(a), hb = __float2bfloat16_rn(b);
    h = pack2(ha, hb);
    l = pack2(__float2bfloat16_rn(a - __bfloat162float(ha)),
              __float2bfloat16_rn(b - __bfloat162float(hb)));
}
__device__ __forceinline__ void ldmx4(uint32_t r[4], uint32_t a) {
    asm volatile("ldmatrix.sync.aligned.m8n8.x4.shared.b16 {%0,%1,%2,%3}, [%4];"
                 : "=r"(r[0]), "=r"(r[1]), "=r"(r[2]), "=r"(r[3]) : "r"(a));
}
__device__ __forceinline__ void mma_bf16(float d[4], const uint32_t a[4],
                                         const uint32_t b[2]) {
    asm volatile("mma.sync.aligned.m16n8k16.row.col.f32.bf16.bf16.f32 "
                 "{%0,%1,%2,%3},{%4,%5,%6,%7},{%8,%9},{%0,%1,%2,%3};"
                 : "+f"(d[0]), "+f"(d[1]), "+f"(d[2]), "+f"(d[3])
                 : "r"(a[0]), "r"(a[1]), "r"(a[2]), "r"(a[3]),
                   "r"(b[0]), "r"(b[1]));
}
#define CP_ASYNC(dst, src) \
    asm volatile("cp.async.cg.shared.global [%0], [%1], 16;" :: "r"(dst), "l"(src))
#define CP_COMMIT() asm volatile("cp.async.commit_group;" ::: "memory")

// ================= k1: norm_scale = cond @ w_cond.T + 1 =================
__global__ void k_cond(const float* __restrict__ cond,
                       const float* __restrict__ w_cond) {
    int w    = (blockIdx.x * blockDim.x + threadIdx.x) >> 5;
    int lane = threadIdx.x & 31;
    if (w >= 2 * DM) return;
    int n = w >> 9, c = w & 511;
    const float* cp = cond + n * CND;
    const float* wp = w_cond + c * CND;
    float s = 0.f;
    #pragma unroll 4
    for (int k = lane; k < CND; k += 32) s += cp[k] * wp[k];
    #pragma unroll
    for (int o = 16; o; o >>= 1) s += __shfl_xor_sync(~0u, s, o);
    if (!lane) g_nscale[w] = s + 1.0f;
}

// ===== k2: fused per-token RMS + scale + bf16 hi/lo convert of A =====
__global__ void k_prep_a(const float* __restrict__ x) {
    int wid = threadIdx.x >> 5, lane = threadIdx.x & 31;
    int row = blockIdx.x * 8 + wid;
    const float4* xp = (const float4*)(x + (size_t)row * DM);
    float4 vv[4];
    float s = 0.f;
    #pragma unroll
    for (int i = 0; i < 4; i++) {
        vv[i] = xp[i * 32 + lane];
        s += vv[i].x * vv[i].x + vv[i].y * vv[i].y +
             vv[i].z * vv[i].z + vv[i].w * vv[i].w;
    }
    #pragma unroll
    for (int o = 16; o; o >>= 1) s += __shfl_xor_sync(~0u, s, o);
    float rstd = rsqrtf(s * (1.0f / DM) + 1e-6f);
    const float* nsc = g_nscale + (row >> 10) * DM;
    #pragma unroll
    for (int i = 0; i < 4; i++) {
        int c0 = (i * 32 + lane) * 4;
        float a = vv[i].x * rstd * nsc[c0];
        float b = vv[i].y * rstd * nsc[c0 + 1];
        float c = vv[i].z * rstd * nsc[c0 + 2];
        float d = vv[i].w * rstd * nsc[c0 + 3];
        uint32_t h0, l0, h1, l1;
        split2(a, b, h0, l0);
        split2(c, d, h1, l1);
        *(uint2*)(g_ah + (size_t)row * DM + c0) = make_uint2(h0, h1);
        *(uint2*)(g_al + (size_t)row * DM + c0) = make_uint2(l0, l1);
    }
}

// ===== weight fp32 -> bf16 hi/lo converter (into g_bh/g_bl) =====
__global__ void k_cvt_b(const float* __restrict__ src, int total) {
    int idx = (blockIdx.x * 256 + threadIdx.x) * 4;
    if (idx >= total) return;
    float4 v = *(const float4*)(src + idx);
    uint32_t h0, l0, h1, l1;
    split2(v.x, v.y, h0, l0);
    split2(v.z, v.w, h1, l1);
    *(uint2*)(g_bh + idx) = make_uint2(h0, h1);
    *(uint2*)(g_bl + idx) = make_uint2(l0, l1);
}

// ====== bf16 3-term split GEMM via mma.sync, cp.async 3-stage pipeline ======
// Template: BM in {128, 64}, BN = 64, BK = 32. 8 warps in 4(m) x 2(n),
// warp tile (BM/4) x 32. Stage = Ah,Al (BM x 32) + Bh,Bl (64 x 32) bf16.
// MODE 0: C = A@Wqkv^T, scatter into g_q/g_k/g_v head-major.
// MODE 1: C = A@Wout^T + skip -> outp.
template <int MODE, int BM>
__global__ __launch_bounds__(256, 3) void k_mm(const float* __restrict__ skip,
                                               float* __restrict__ outp) {
    constexpr int PLN_A  = BM * 64;            // bytes per A plane
    constexpr int OFF_AL = PLN_A;
    constexpr int OFF_BH = 2 * PLN_A;
    constexpr int OFF_BL = 2 * PLN_A + 4096;
    constexpr int STG    = 2 * PLN_A + 8192;
    constexpr int MT     = BM / 64;            // m16-tiles per warp

    extern __shared__ char smem[];
    const uint32_t sb = smem_u32(smem);
    const int t = threadIdx.x, lane = t & 31, wid = t >> 5;
    const int m0 = blockIdx.y * BM, n0 = blockIdx.x * 64;
    const int mbase = (wid >> 1) * (BM / 4), nbase = (wid & 1) * 32;
    const int qy = lane >> 2, t4 = lane & 3;

    float acc[MT][4][4];
    #pragma unroll
    for (int i = 0; i < MT; i++)
        #pragma unroll
        for (int j = 0; j < 4; j++)
            #pragma unroll
            for (int r = 0; r < 4; r++) acc[i][j][r] = 0.f;

    auto issue = [&](int s) {
        if (s < 16) {
            int k0 = s * 32;
            uint32_t stb = sb + (s % 3) * STG;
            #pragma unroll
            for (int i = 0; i < BM / 64; i++) {   // A planes
                int rc = i * 256 + t;
                int row = rc >> 2, c = rc & 3;
                int phys = (c + (row >> 1)) & 3;
                uint32_t dst = stb + row * 64 + phys * 16;
                CP_ASYNC(dst, g_ah + (size_t)(m0 + row) * DM + k0 + c * 8);
                CP_ASYNC(dst + OFF_AL, g_al + (size_t)(m0 + row) * DM + k0 + c * 8);
            }
            {                                      // B planes (64 rows)
                int row = t >> 2, c = t & 3;
                int phys = (c + (row >> 1)) & 3;
                uint32_t dst = stb + OFF_BH + row * 64 + phys * 16;
                CP_ASYNC(dst, g_bh + (size_t)(n0 + row) * DM + k0 + c * 8);
                CP_ASYNC(dst + 4096, g_bl + (size_t)(n0 + row) * DM + k0 + c * 8);
            }
        }
        CP_COMMIT();
    };

    issue(0); issue(1);

    for (int it = 0; it < 16; ++it) {
        if (it < 15) asm volatile("cp.async.wait_group 1;" ::: "memory");
        else         asm volatile("cp.async.wait_group 0;" ::: "memory");
        __syncthreads();
        uint32_t stb = sb + (it % 3) * STG;
        #pragma unroll
        for (int kk = 0; kk < 2; ++kk) {
            uint32_t ah[MT][4], al[MT][4], bh[4][2], bl[4][2];
            #pragma unroll
            for (int mt = 0; mt < MT; ++mt) {
                int row = mbase + mt * 16 + (lane & 15);
                int c = kk * 2 + (lane >> 4);
                int phys = (c + (row >> 1)) & 3;
                uint32_t ad = stb + row * 64 + phys * 16;
                ldmx4(ah[mt], ad);
                ldmx4(al[mt], ad + OFF_AL);
            }
            #pragma unroll
            for (int p = 0; p < 2; ++p) {          // two n16 groups -> 4 n8 tiles
                int row = nbase + p * 16 + (lane & 15);
                int c = kk * 2 + (lane >> 4);
                int phys = (c + (row >> 1)) & 3;
                uint32_t ad = stb + OFF_BH + row * 64 + phys * 16;
                uint32_t r4[4];
                ldmx4(r4, ad);
                bh[2 * p][0] = r4[0]; bh[2 * p][1] = r4[2];
                bh[2 * p + 1][0] = r4[1]; bh[2 * p + 1][1] = r4[3];
                ldmx4(r4, ad + 4096);
                bl[2 * p][0] = r4[0]; bl[2 * p][1] = r4[2];
                bl[2 * p + 1][0] = r4[1]; bl[2 * p + 1][1] = r4[3];
            }
            #pragma unroll
            for (int mt = 0; mt < MT; ++mt)
                #pragma unroll
                for (int nt = 0; nt < 4; ++nt) mma_bf16(acc[mt][nt], ah[mt], bh[nt]);
            #pragma unroll
            for (int mt = 0; mt < MT; ++mt)
                #pragma unroll
                for (int nt = 0; nt < 4; ++nt) mma_bf16(acc[mt][nt], al[mt], bh[nt]);
            #pragma unroll
            for (int mt = 0; mt < MT; ++mt)
                #pragma unroll
                for (int nt = 0; nt < 4; ++nt) mma_bf16(acc[mt][nt], ah[mt], bl[nt]);
        }
        issue(it + 2);
    }

    // ---- epilogue ----
    const int nb = m0 >> 10;
    #pragma unroll
    for (int mt = 0; mt < MT; ++mt) {
        int r0 = m0 + mbase + mt * 16 + qy;
        #pragma unroll
        for (int nt = 0; nt < 4; ++nt) {
            int col = n0 + nbase + nt * 8 + 2 * t4;
            if (MODE == 0) {
                int part = col >> 9;
                int head = (col >> 6) & 7;
                int d0   = col & 63;
                int ij0  = r0 & 1023, ij1 = (r0 + 8) & 1023;
                float* dst = ((part == 0) ? g_q : (part == 1) ? g_k : g_v)
                             + ((size_t)(nb * NH + head) * 1024) * DH + d0;
                float2 v0 = {acc[mt][nt][0], acc[mt][nt][1]};
                float2 v1 = {acc[mt][nt][2], acc[mt][nt][3]};
                *(float2*)(dst + (size_t)ij0 * DH) = v0;
                *(float2*)(dst + (size_t)ij1 * DH) = v1;
            } else {
                float2 s0 = *(const float2*)(skip + (size_t)r0 * DM + col);
                float2 s1 = *(const float2*)(skip + (size_t)(r0 + 8) * DM + col);
                float2 v0 = {acc[mt][nt][0] + s0.x, acc[mt][nt][1] + s0.y};
                float2 v1 = {acc[mt][nt][2] + s1.x, acc[mt][nt][3] + s1.y};
                *(float2*)(outp + (size_t)r0 * DM + col)       = v0;
                *(float2*)(outp + (size_t)(r0 + 8) * DM + col) = v1;
            }
        }
    }
}

// ====== k4: per-head L2 norm + RoPE ======
__global__ void k_rope(const float* __restrict__ pos,
                       const float* __restrict__ scale) {
    int w    = (blockIdx.x * blockDim.x + threadIdx.x) >> 5;
    int lane = threadIdx.x & 31;
    const int total = 2 * NH * 1024;
    if (w >= 2 * total) return;
    float* buf = (w < total) ? g_q : g_k;
    int v  = (w < total) ? w : w - total;
    int n  = v >> 13;
    int h  = (v >> 10) & 7;
    int ij = v & 1023;
    float* p = buf + (size_t)v * DH;

    float a = p[lane];
    float b = p[lane + 32];
    float s = a * a + b * b;
    #pragma unroll
    for (int o = 16; o; o >>= 1) s += __shfl_xor_sync(~0u, s, o);
    float fac = sqrtf(scale[h]) * rsqrtf(s + 1e-6f);
    a *= fac;
    b *= fac;

    int m = lane & 15;
    float freq = 3.14159265358979f * __expf((float)(m * 8 + h) * (2.302585092994046f / 128.0f));
    float th = pos[n * 1024 + ij] * freq;
    float sn, cs;
    __sincosf(th, &sn, &cs);
    float partner = __shfl_xor_sync(~0u, a, 16);
    float na = (lane < 16) ? (a * cs - partner * sn) : (a * cs + partner * sn);
    p[lane]      = na;
    p[lane + 32] = b;
}

// ====== k5: 7x7 neighborhood attention (fp32, writes bf16 hi/lo planes) ======
__global__ __launch_bounds__(256, 2) void k_attn() {
    extern __shared__ float sm[];
    float* Ks = sm;
    float* Vs = sm + 196 * PAD;
    int b    = blockIdx.x;
    int tile = b & 15;
    int h    = (b >> 4) & 7;
    int n    = b >> 7;
    int i0 = (tile >> 2) * 8, j0 = (tile & 3) * 8;
    int rbase = min(max(i0 - 3, 0), 18);
    int cbase = min(max(j0 - 3, 0), 18);

    const float* kb = g_k + (size_t)((n * NH + h) * 1024) * DH;
    const float* vb = g_v + (size_t)((n * NH + h) * 1024) * DH;

    for (int idx = threadIdx.x; idx < 196 * 16; idx += 256) {
        int px = idx >> 4, u = idx & 15;
        int r = px / 14, cc = px - r * 14;
        int g = ((rbase + r) * 32 + cbase + cc) * 16 + u;
        ((float4*)(Ks + px * PAD))[u] = ((const float4*)kb)[g];
        ((float4*)(Vs + px * PAD))[u] = ((const float4*)vb)[g];
    }
    __syncthreads();

    int p = threadIdx.x >> 2, s = threadIdx.x & 3;
    int gi = i0 + (p >> 3), gj = j0 + (p & 7);
    int si = min(max(gi - 3, 0), 25) - rbase;
    int sj = min(max(gj - 3, 0), 25) - cbase;

    const float* qp = g_q + ((size_t)((n * NH + h) * 1024) + gi * 32 + gj) * DH + s * 16;
    float4 q0 = ((const float4*)qp)[0];
    float4 q1 = ((const float4*)qp)[1];
    float4 q2 = ((const float4*)qp)[2];
    float4 q3 = ((const float4*)qp)[3];

    float logit[49];
    #pragma unroll
    for (int a = 0; a < 7; a++) {
        #pragma unroll
        for (int bb = 0; bb < 7; bb++) {
            const float* kp = Ks + ((si + a) * 14 + sj + bb) * PAD + s * 16;
            float4 c0 = ((const float4*)kp)[0];
            float4 c1 = ((const float4*)kp)[1];
            float4 c2 = ((const float4*)kp)[2];
            float4 c3 = ((const float4*)kp)[3];
            float d = q0.x * c0.x + q0.y * c0.y + q0.z * c0.z + q0.w * c0.w
                    + q1.x * c1.x + q1.y * c1.y + q1.z * c1.z + q1.w * c1.w
                    + q2.x * c2.x + q2.y * c2.y + q2.z * c2.z + q2.w * c2.w
                    + q3.x * c3.x + q3.y * c3.y + q3.z * c3.z + q3.w * c3.w;
            d += __shfl_xor_sync(~0u, d, 1);
            d += __shfl_xor_sync(~0u, d, 2);
            logit[a * 7 + bb] = d;
        }
    }

    float mx = -1e30f;
    #pragma unroll
    for (int i = 0; i < 49; i++) mx = fmaxf(mx, logit[i]);
    float sum = 0.f;
    #pragma unroll
    for (int i = 0; i < 49; i++) {
        float e = __expf(logit[i] - mx);
        logit[i] = e;
        sum += e;
    }
    float inv = 1.0f / sum;

    float acc[16];
    #pragma unroll
    for (int j = 0; j < 16; j++) acc[j] = 0.f;
    #pragma unroll
    for (int a = 0; a < 7; a++) {
        #pragma unroll
        for (int bb = 0; bb < 7; bb++) {
            float wgt = logit[a * 7 + bb];
            const float* vp = Vs + ((si + a) * 14 + sj + bb) * PAD + s * 16;
            #pragma unroll
            for (int j = 0; j < 16; j++) acc[j] += wgt * vp[j];
        }
    }

    // write attention output directly as bf16 hi/lo planes (A of out GEMM)
    size_t off = (size_t)(n * 1024 + gi * 32 + gj) * DM + h * DH + s * 16;
    uint32_t hw[8], lw[8];
    #pragma unroll
    for (int u = 0; u < 8; ++u)
        split2(acc[2 * u] * inv, acc[2 * u + 1] * inv, hw[u], lw[u]);
    *(uint4*)(g_ah + off)     = make_uint4(hw[0], hw[1], hw[2], hw[3]);
    *(uint4*)(g_ah + off + 8) = make_uint4(hw[4], hw[5], hw[6], hw[7]);
    *(uint4*)(g_al + off)     = make_uint4(lw[0], lw[1], lw[2], lw[3]);
    *(uint4*)(g_al + off + 8) = make_uint4(lw[4], lw[5], lw[6], lw[7]);
}

// =========================== launch ===========================
extern "C" void kernel_launch(void* const* d_in, const int* in_sizes, int n_in,
                              void* d_out, int out_size) {
    const float* x      = (const float*)d_in[0];
    const float* pos    = (const float*)d_in[1];
    const float* cond   = (const float*)d_in[2];
    const float* w_cond = (const float*)d_in[3];
    const float* w_qkv  = (const float*)d_in[4];
    const float* scale  = (const float*)d_in[5];
    const float* w_out  = (const float*)d_in[6];
    float* out = (float*)d_out;

    const int attn_smem = 2 * 196 * PAD * 4;
    const int mm0_smem = 3 * (2 * 128 * 64 + 8192);  // 73728
    const int mm1_smem = 3 * (2 * 64 * 64 + 8192);   // 49152
    cudaFuncSetAttribute(k_attn, cudaFuncAttributeMaxDynamicSharedMemorySize,
                         attn_smem);
    cudaFuncSetAttribute((const void*)k_mm<0, 128>,
                         cudaFuncAttributeMaxDynamicSharedMemorySize, mm0_smem);
    cudaFuncSetAttribute((const void*)k_mm<1, 64>,
                         cudaFuncAttributeMaxDynamicSharedMemorySize, mm1_smem);

    k_cond<<<128, 256>>>(cond, w_cond);
    k_prep_a<<<256, 256>>>(x);
    k_cvt_b<<<768, 256>>>(w_qkv, 3 * DM * DM);
    k_mm<0, 128><<<dim3(24, 16), 256, mm0_smem>>>(nullptr, nullptr);
    k_rope<<<4096, 256>>>(pos, scale);
    k_attn<<<256, 256, attn_smem>>>();
    k_cvt_b<<<256, 256>>>(w_out, DM * DM);   // w_out -> g_bh/g_bl
    k_mm<1, 64><<<dim3(8, 32), 256, mm1_smem>>>(x, out);
}

// round 13
// speedup vs baseline: 2.3448x; 1.0606x over previous
#include <cuda_runtime.h>
#include <cuda_bf16.h>
#include <math.h>
#include <stdint.h>

#define NTOK 2048
#define DM   512
#define NH   8
#define DH   64
#define CND  768
#define PAD  68

// -------- scratch (device globals; no allocation allowed) --------
__device__ float g_nscale[2 * DM];
__device__ __align__(16) float g_q[2 * NH * 1024 * DH];
__device__ __align__(16) float g_k[2 * NH * 1024 * DH];
__device__ __align__(16) float g_v[2 * NH * 1024 * DH];
// bf16 hi/lo planes
__device__ __align__(16) __nv_bfloat16 g_ah[NTOK * DM];
__device__ __align__(16) __nv_bfloat16 g_al[NTOK * DM];
__device__ __align__(16) __nv_bfloat16 g_bh[3 * DM * DM];
__device__ __align__(16) __nv_bfloat16 g_bl[3 * DM * DM];

// ---------------- helpers ----------------
__device__ __forceinline__ uint32_t smem_u32(const void* p) {
    uint32_t a;
    asm("{ .reg .u64 t; cvta.to.shared.u64 t, %1; cvt.u32.u64 %0, t; }"
        : "=r"(a) : "l"(p));
    return a;
}
__device__ __forceinline__ uint32_t pack2(__nv_bfloat16 a, __nv_bfloat16 b) {
    __nv_bfloat162 t = __halves2bfloat162(a, b);
    return *reinterpret_cast<uint32_t*>(&t);
}
__device__ __forceinline__ void split2(float a, float b, uint32_t& h, uint32_t& l) {
    __nv_bfloat16 ha = __float2bfloat16_rn(a), hb = __float2bfloat16_rn(b);
    h = pack2(ha, hb);
    l = pack2(__float2bfloat16_rn(a - __bfloat162float(ha)),
              __float2bfloat16_rn(b - __bfloat162float(hb)));
}
__device__ __forceinline__ void ldmx4(uint32_t r[4], uint32_t a) {
    asm volatile("ldmatrix.sync.aligned.m8n8.x4.shared.b16 {%0,%1,%2,%3}, [%4];"
                 : "=r"(r[0]), "=r"(r[1]), "=r"(r[2]), "=r"(r[3]) : "r"(a));
}
__device__ __forceinline__ void mma_bf16(float d[4], const uint32_t a[4],
                                         const uint32_t b[2]) {
    asm volatile("mma.sync.aligned.m16n8k16.row.col.f32.bf16.bf16.f32 "
                 "{%0,%1,%2,%3},{%4,%5,%6,%7},{%8,%9},{%0,%1,%2,%3};"
                 : "+f"(d[0]), "+f"(d[1]), "+f"(d[2]), "+f"(d[3])
                 : "r"(a[0]), "r"(a[1]), "r"(a[2]), "r"(a[3]),
                   "r"(b[0]), "r"(b[1]));
}
// packed f32x2 FMA (FFMA2)
__device__ __forceinline__ unsigned long long fma2(unsigned long long a,
                                                   unsigned long long b,
                                                   unsigned long long c) {
    unsigned long long d;
    asm("fma.rn.f32x2 %0, %1, %2, %3;" : "=l"(d) : "l"(a), "l"(b), "l"(c));
    return d;
}
__device__ __forceinline__ unsigned long long pk2(float x, float y) {
    unsigned long long r;
    asm("mov.b64 %0, {%1,%2};" : "=l"(r) : "f"(x), "f"(y));
    return r;
}
__device__ __forceinline__ float2 upk2(unsigned long long v) {
    float2 f;
    asm("mov.b64 {%0,%1}, %2;" : "=f"(f.x), "=f"(f.y) : "l"(v));
    return f;
}
#define CP_ASYNC(dst, src) \
    asm volatile("cp.async.cg.shared.global [%0], [%1], 16;" :: "r"(dst), "l"(src))
#define CP_COMMIT() asm volatile("cp.async.commit_group;" ::: "memory")

// ================= k1: norm_scale = cond @ w_cond.T + 1 =================
__global__ void k_cond(const float* __restrict__ cond,
                       const float* __restrict__ w_cond) {
    int w    = (blockIdx.x * blockDim.x + threadIdx.x) >> 5;
    int lane = threadIdx.x & 31;
    if (w >= 2 * DM) return;
    int n = w >> 9, c = w & 511;
    const float* cp = cond + n * CND;
    const float* wp = w_cond + c * CND;
    float s = 0.f;
    #pragma unroll 4
    for (int k = lane; k < CND; k += 32) s += cp[k] * wp[k];
    #pragma unroll
    for (int o = 16; o; o >>= 1) s += __shfl_xor_sync(~0u, s, o);
    if (!lane) g_nscale[w] = s + 1.0f;
}

// ===== k2: fused per-token RMS + scale + bf16 hi/lo convert of A =====
__global__ void k_prep_a(const float* __restrict__ x) {
    int wid = threadIdx.x >> 5, lane = threadIdx.x & 31;
    int row = blockIdx.x * 8 + wid;
    const float4* xp = (const float4*)(x + (size_t)row * DM);
    float4 vv[4];
    float s = 0.f;
    #pragma unroll
    for (int i = 0; i < 4; i++) {
        vv[i] = xp[i * 32 + lane];
        s += vv[i].x * vv[i].x + vv[i].y * vv[i].y +
             vv[i].z * vv[i].z + vv[i].w * vv[i].w;
    }
    #pragma unroll
    for (int o = 16; o; o >>= 1) s += __shfl_xor_sync(~0u, s, o);
    float rstd = rsqrtf(s * (1.0f / DM) + 1e-6f);
    const float* nsc = g_nscale + (row >> 10) * DM;
    #pragma unroll
    for (int i = 0; i < 4; i++) {
        int c0 = (i * 32 + lane) * 4;
        float a = vv[i].x * rstd * nsc[c0];
        float b = vv[i].y * rstd * nsc[c0 + 1];
        float c = vv[i].z * rstd * nsc[c0 + 2];
        float d = vv[i].w * rstd * nsc[c0 + 3];
        uint32_t h0, l0, h1, l1;
        split2(a, b, h0, l0);
        split2(c, d, h1, l1);
        *(uint2*)(g_ah + (size_t)row * DM + c0) = make_uint2(h0, h1);
        *(uint2*)(g_al + (size_t)row * DM + c0) = make_uint2(l0, l1);
    }
}

// ===== weight fp32 -> bf16 converter. LO: also write lo plane =====
template <int LO>
__global__ void k_cvt_b(const float* __restrict__ src, int total) {
    int idx = (blockIdx.x * 256 + threadIdx.x) * 4;
    if (idx >= total) return;
    float4 v = *(const float4*)(src + idx);
    uint32_t h0, l0, h1, l1;
    split2(v.x, v.y, h0, l0);
    split2(v.z, v.w, h1, l1);
    *(uint2*)(g_bh + idx) = make_uint2(h0, h1);
    if (LO) *(uint2*)(g_bl + idx) = make_uint2(l0, l1);
}

// ====== bf16 split GEMM via mma.sync, cp.async 3-stage pipeline ======
// BM in {128,64}, BN=64, BK=32. 8 warps 4(m)x2(n), warp tile (BM/4)x32.
// TERMS=3: D = Ah*Bh + Al*Bh + Ah*Bl (fp32 fidelity). TERMS=1: D = Ah*Bh.
// MODE 0: scatter into g_q/g_k/g_v head-major. MODE 1: += skip -> outp.
template <int MODE, int BM, int TERMS>
__global__ __launch_bounds__(256, 3) void k_mm(const float* __restrict__ skip,
                                               float* __restrict__ outp) {
    constexpr int PLN_A  = BM * 64;           // bytes per A plane
    constexpr int NPA    = (TERMS == 3) ? 2 : 1;
    constexpr int OFF_B  = NPA * PLN_A;
    constexpr int STG    = OFF_B + ((TERMS == 3) ? 8192 : 4096);
    constexpr int MT     = BM / 64;           // m16-tiles per warp

    extern __shared__ char smem[];
    const uint32_t sb = smem_u32(smem);
    const int t = threadIdx.x, lane = t & 31, wid = t >> 5;
    const int m0 = blockIdx.y * BM, n0 = blockIdx.x * 64;
    const int mbase = (wid >> 1) * (BM / 4), nbase = (wid & 1) * 32;
    const int qy = lane >> 2, t4 = lane & 3;

    float acc[MT][4][4];
    #pragma unroll
    for (int i = 0; i < MT; i++)
        #pragma unroll
        for (int j = 0; j < 4; j++)
            #pragma unroll
            for (int r = 0; r < 4; r++) acc[i][j][r] = 0.f;

    auto issue = [&](int s) {
        if (s < 16) {
            int k0 = s * 32;
            uint32_t stb = sb + (s % 3) * STG;
            #pragma unroll
            for (int i = 0; i < BM / 64; i++) {   // A planes
                int rc = i * 256 + t;
                int row = rc >> 2, c = rc & 3;
                int phys = (c + (row >> 1)) & 3;
                uint32_t dst = stb + row * 64 + phys * 16;
                CP_ASYNC(dst, g_ah + (size_t)(m0 + row) * DM + k0 + c * 8);
                if (TERMS == 3)
                    CP_ASYNC(dst + PLN_A, g_al + (size_t)(m0 + row) * DM + k0 + c * 8);
            }
            {                                      // B planes (64 rows)
                int row = t >> 2, c = t & 3;
                int phys = (c + (row >> 1)) & 3;
                uint32_t dst = stb + OFF_B + row * 64 + phys * 16;
                CP_ASYNC(dst, g_bh + (size_t)(n0 + row) * DM + k0 + c * 8);
                if (TERMS == 3)
                    CP_ASYNC(dst + 4096, g_bl + (size_t)(n0 + row) * DM + k0 + c * 8);
            }
        }
        CP_COMMIT();
    };

    issue(0); issue(1);

    for (int it = 0; it < 16; ++it) {
        if (it < 15) asm volatile("cp.async.wait_group 1;" ::: "memory");
        else         asm volatile("cp.async.wait_group 0;" ::: "memory");
        __syncthreads();
        uint32_t stb = sb + (it % 3) * STG;
        #pragma unroll
        for (int kk = 0; kk < 2; ++kk) {
            uint32_t ah[MT][4], al[MT][4], bh[4][2], bl[4][2];
            #pragma unroll
            for (int mt = 0; mt < MT; ++mt) {
                int row = mbase + mt * 16 + (lane & 15);
                int c = kk * 2 + (lane >> 4);
                int phys = (c + (row >> 1)) & 3;
                uint32_t ad = stb + row * 64 + phys * 16;
                ldmx4(ah[mt], ad);
                if (TERMS == 3) ldmx4(al[mt], ad + PLN_A);
            }
            #pragma unroll
            for (int p = 0; p < 2; ++p) {
                int row = nbase + p * 16 + (lane & 15);
                int c = kk * 2 + (lane >> 4);
                int phys = (c + (row >> 1)) & 3;
                uint32_t ad = stb + OFF_B + row * 64 + phys * 16;
                uint32_t r4[4];
                ldmx4(r4, ad);
                bh[2 * p][0] = r4[0]; bh[2 * p][1] = r4[2];
                bh[2 * p + 1][0] = r4[1]; bh[2 * p + 1][1] = r4[3];
                if (TERMS == 3) {
                    ldmx4(r4, ad + 4096);
                    bl[2 * p][0] = r4[0]; bl[2 * p][1] = r4[2];
                    bl[2 * p + 1][0] = r4[1]; bl[2 * p + 1][1] = r4[3];
                }
            }
            #pragma unroll
            for (int mt = 0; mt < MT; ++mt)
                #pragma unroll
                for (int nt = 0; nt < 4; ++nt) mma_bf16(acc[mt][nt], ah[mt], bh[nt]);
            if (TERMS == 3) {
                #pragma unroll
                for (int mt = 0; mt < MT; ++mt)
                    #pragma unroll
                    for (int nt = 0; nt < 4; ++nt) mma_bf16(acc[mt][nt], al[mt], bh[nt]);
                #pragma unroll
                for (int mt = 0; mt < MT; ++mt)
                    #pragma unroll
                    for (int nt = 0; nt < 4; ++nt) mma_bf16(acc[mt][nt], ah[mt], bl[nt]);
            }
        }
        issue(it + 2);
    }

    // ---- epilogue ----
    const int nb = m0 >> 10;
    #pragma unroll
    for (int mt = 0; mt < MT; ++mt) {
        int r0 = m0 + mbase + mt * 16 + qy;
        #pragma unroll
        for (int nt = 0; nt < 4; ++nt) {
            int col = n0 + nbase + nt * 8 + 2 * t4;
            if (MODE == 0) {
                int part = col >> 9;
                int head = (col >> 6) & 7;
                int d0   = col & 63;
                int ij0  = r0 & 1023, ij1 = (r0 + 8) & 1023;
                float* dst = ((part == 0) ? g_q : (part == 1) ? g_k : g_v)
                             + ((size_t)(nb * NH + head) * 1024) * DH + d0;
                float2 v0 = {acc[mt][nt][0], acc[mt][nt][1]};
                float2 v1 = {acc[mt][nt][2], acc[mt][nt][3]};
                *(float2*)(dst + (size_t)ij0 * DH) = v0;
                *(float2*)(dst + (size_t)ij1 * DH) = v1;
            } else {
                float2 s0 = *(const float2*)(skip + (size_t)r0 * DM + col);
                float2 s1 = *(const float2*)(skip + (size_t)(r0 + 8) * DM + col);
                float2 v0 = {acc[mt][nt][0] + s0.x, acc[mt][nt][1] + s0.y};
                float2 v1 = {acc[mt][nt][2] + s1.x, acc[mt][nt][3] + s1.y};
                *(float2*)(outp + (size_t)r0 * DM + col)       = v0;
                *(float2*)(outp + (size_t)(r0 + 8) * DM + col) = v1;
            }
        }
    }
}

// ====== k4: per-head L2 norm + RoPE ======
__global__ void k_rope(const float* __restrict__ pos,
                       const float* __restrict__ scale) {
    int w    = (blockIdx.x * blockDim.x + threadIdx.x) >> 5;
    int lane = threadIdx.x & 31;
    const int total = 2 * NH * 1024;
    if (w >= 2 * total) return;
    float* buf = (w < total) ? g_q : g_k;
    int v  = (w < total) ? w : w - total;
    int n  = v >> 13;
    int h  = (v >> 10) & 7;
    int ij = v & 1023;
    float* p = buf + (size_t)v * DH;

    float a = p[lane];
    float b = p[lane + 32];
    float s = a * a + b * b;
    #pragma unroll
    for (int o = 16; o; o >>= 1) s += __shfl_xor_sync(~0u, s, o);
    float fac = sqrtf(scale[h]) * rsqrtf(s + 1e-6f);
    a *= fac;
    b *= fac;

    int m = lane & 15;
    float freq = 3.14159265358979f * __expf((float)(m * 8 + h) * (2.302585092994046f / 128.0f));
    float th = pos[n * 1024 + ij] * freq;
    float sn, cs;
    __sincosf(th, &sn, &cs);
    float partner = __shfl_xor_sync(~0u, a, 16);
    float na = (lane < 16) ? (a * cs - partner * sn) : (a * cs + partner * sn);
    p[lane]      = na;
    p[lane + 32] = b;
}

// ====== k5: 7x7 neighborhood attention (FFMA2 packed fp32) ======
__global__ __launch_bounds__(256, 2) void k_attn() {
    extern __shared__ float sm[];
    float* Ks = sm;
    float* Vs = sm + 196 * PAD;
    int b    = blockIdx.x;
    int tile = b & 15;
    int h    = (b >> 4) & 7;
    int n    = b >> 7;
    int i0 = (tile >> 2) * 8, j0 = (tile & 3) * 8;
    int rbase = min(max(i0 - 3, 0), 18);
    int cbase = min(max(j0 - 3, 0), 18);

    const float* kb = g_k + (size_t)((n * NH + h) * 1024) * DH;
    const float* vb = g_v + (size_t)((n * NH + h) * 1024) * DH;

    for (int idx = threadIdx.x; idx < 196 * 16; idx += 256) {
        int px = idx >> 4, u = idx & 15;
        int r = px / 14, cc = px - r * 14;
        int g = ((rbase + r) * 32 + cbase + cc) * 16 + u;
        ((float4*)(Ks + px * PAD))[u] = ((const float4*)kb)[g];
        ((float4*)(Vs + px * PAD))[u] = ((const float4*)vb)[g];
    }
    __syncthreads();

    int p = threadIdx.x >> 2, s = threadIdx.x & 3;
    int gi = i0 + (p >> 3), gj = j0 + (p & 7);
    int si = min(max(gi - 3, 0), 25) - rbase;
    int sj = min(max(gj - 3, 0), 25) - cbase;

    const float* qp = g_q + ((size_t)((n * NH + h) * 1024) + gi * 32 + gj) * DH + s * 16;
    ulonglong2 q01 = ((const ulonglong2*)qp)[0];
    ulonglong2 q23 = ((const ulonglong2*)qp)[1];
    ulonglong2 q45 = ((const ulonglong2*)qp)[2];
    ulonglong2 q67 = ((const ulonglong2*)qp)[3];

    float logit[49];
    #pragma unroll
    for (int a = 0; a < 7; a++) {
        #pragma unroll
        for (int bb = 0; bb < 7; bb++) {
            const ulonglong2* kp =
                (const ulonglong2*)(Ks + ((si + a) * 14 + sj + bb) * PAD + s * 16);
            ulonglong2 k01 = kp[0], k23 = kp[1], k45 = kp[2], k67 = kp[3];
            unsigned long long a2 = 0ull;
            a2 = fma2(q01.x, k01.x, a2);
            a2 = fma2(q01.y, k01.y, a2);
            a2 = fma2(q23.x, k23.x, a2);
            a2 = fma2(q23.y, k23.y, a2);
            a2 = fma2(q45.x, k45.x, a2);
            a2 = fma2(q45.y, k45.y, a2);
            a2 = fma2(q67.x, k67.x, a2);
            a2 = fma2(q67.y, k67.y, a2);
            float2 f = upk2(a2);
            float d = f.x + f.y;
            d += __shfl_xor_sync(~0u, d, 1);
            d += __shfl_xor_sync(~0u, d, 2);
            logit[a * 7 + bb] = d;
        }
    }

    float mx = -1e30f;
    #pragma unroll
    for (int i = 0; i < 49; i++) mx = fmaxf(mx, logit[i]);
    float sum = 0.f;
    #pragma unroll
    for (int i = 0; i < 49; i++) {
        float e = __expf(logit[i] - mx);
        logit[i] = e;
        sum += e;
    }
    float inv = 1.0f / sum;

    unsigned long long acc2[8];
    #pragma unroll
    for (int j = 0; j < 8; j++) acc2[j] = 0ull;
    #pragma unroll
    for (int a = 0; a < 7; a++) {
        #pragma unroll
        for (int bb = 0; bb < 7; bb++) {
            float wgt = logit[a * 7 + bb];
            unsigned long long w2 = pk2(wgt, wgt);
            const ulonglong2* vp =
                (const ulonglong2*)(Vs + ((si + a) * 14 + sj + bb) * PAD + s * 16);
            ulonglong2 v01 = vp[0], v23 = vp[1], v45 = vp[2], v67 = vp[3];
            acc2[0] = fma2(w2, v01.x, acc2[0]);
            acc2[1] = fma2(w2, v01.y, acc2[1]);
            acc2[2] = fma2(w2, v23.x, acc2[2]);
            acc2[3] = fma2(w2, v23.y, acc2[3]);
            acc2[4] = fma2(w2, v45.x, acc2[4]);
            acc2[5] = fma2(w2, v45.y, acc2[5]);
            acc2[6] = fma2(w2, v67.x, acc2[6]);
            acc2[7] = fma2(w2, v67.y, acc2[7]);
        }
    }

    // write attention output directly as bf16 hi plane (1-term out GEMM)
    size_t off = (size_t)(n * 1024 + gi * 32 + gj) * DM + h * DH + s * 16;
    uint32_t hw[8], lw[8];
    #pragma unroll
    for (int u = 0; u < 8; ++u) {
        float2 f = upk2(acc2[u]);
        split2(f.x * inv, f.y * inv, hw[u], lw[u]);
    }
    *(uint4*)(g_ah + off)     = make_uint4(hw[0], hw[1], hw[2], hw[3]);
    *(uint4*)(g_ah + off + 8) = make_uint4(hw[4], hw[5], hw[6], hw[7]);
}

// =========================== launch ===========================
extern "C" void kernel_launch(void* const* d_in, const int* in_sizes, int n_in,
                              void* d_out, int out_size) {
    const float* x      = (const float*)d_in[0];
    const float* pos    = (const float*)d_in[1];
    const float* cond   = (const float*)d_in[2];
    const float* w_cond = (const float*)d_in[3];
    const float* w_qkv  = (const float*)d_in[4];
    const float* scale  = (const float*)d_in[5];
    const float* w_out  = (const float*)d_in[6];
    float* out = (float*)d_out;

    const int attn_smem = 2 * 196 * PAD * 4;
    const int mm0_smem = 3 * (2 * 128 * 64 + 8192);  // 73728
    const int mm1_smem = 3 * (64 * 64 + 4096);       // 24576
    cudaFuncSetAttribute(k_attn, cudaFuncAttributeMaxDynamicSharedMemorySize,
                         attn_smem);
    cudaFuncSetAttribute((const void*)k_mm<0, 128, 3>,
                         cudaFuncAttributeMaxDynamicSharedMemorySize, mm0_smem);
    cudaFuncSetAttribute((const void*)k_mm<1, 64, 1>,
                         cudaFuncAttributeMaxDynamicSharedMemorySize, mm1_smem);

    k_cond<<<128, 256>>>(cond, w_cond);
    k_prep_a<<<256, 256>>>(x);
    k_cvt_b<1><<<768, 256>>>(w_qkv, 3 * DM * DM);
    k_mm<0, 128, 3><<<dim3(24, 16), 256, mm0_smem>>>(nullptr, nullptr);
    k_rope<<<4096, 256>>>(pos, scale);
    k_attn<<<256, 256, attn_smem>>>();
    k_cvt_b<0><<<256, 256>>>(w_out, DM * DM);   // w_out -> g_bh (hi only)
    k_mm<1, 64, 1><<<dim3(8, 32), 256, mm1_smem>>>(x, out);
}

// round 15
// speedup vs baseline: 2.3627x; 1.0076x over previous
#include <cuda_runtime.h>
#include <cuda_bf16.h>
#include <math.h>
#include <stdint.h>

#define NTOK 2048
#define DM   512
#define NH   8
#define DH   64
#define CND  768
#define PAD  68

// -------- scratch (device globals; no allocation allowed) --------
__device__ float g_nscale[2 * DM];
__device__ __align__(16) float g_q[2 * NH * 1024 * DH];
__device__ __align__(16) float g_k[2 * NH * 1024 * DH];
__device__ __align__(16) float g_v[2 * NH * 1024 * DH];
// bf16 hi/lo planes (B: [w_qkv | w_out] at offset 3*DM*DM)
__device__ __align__(16) __nv_bfloat16 g_ah[NTOK * DM];
__device__ __align__(16) __nv_bfloat16 g_al[NTOK * DM];
__device__ __align__(16) __nv_bfloat16 g_bh[4 * DM * DM];
__device__ __align__(16) __nv_bfloat16 g_bl[4 * DM * DM];

// ---------------- helpers ----------------
__device__ __forceinline__ uint32_t smem_u32(const void* p) {
    uint32_t a;
    asm("{ .reg .u64 t; cvta.to.shared.u64 t, %1; cvt.u32.u64 %0, t; }"
        : "=r"(a) : "l"(p));
    return a;
}
__device__ __forceinline__ uint32_t pack2(__nv_bfloat16 a, __nv_bfloat16 b) {
    __nv_bfloat162 t = __halves2bfloat162(a, b);
    return *reinterpret_cast<uint32_t*>(&t);
}
__device__ __forceinline__ void split2(float a, float b, uint32_t& h, uint32_t& l) {
    __nv_bfloat16 ha = __float2bfloat16_rn(a), hb = __float2bfloat16_rn(b);
    h = pack2(ha, hb);
    l = pack2(__float2bfloat16_rn(a - __bfloat162float(ha)),
              __float2bfloat16_rn(b - __bfloat162float(hb)));
}
__device__ __forceinline__ void ldmx4(uint32_t r[4], uint32_t a) {
    asm volatile("ldmatrix.sync.aligned.m8n8.x4.shared.b16 {%0,%1,%2,%3}, [%4];"
                 : "=r"(r[0]), "=r"(r[1]), "=r"(r[2]), "=r"(r[3]) : "r"(a));
}
__device__ __forceinline__ void mma_bf16(float d[4], const uint32_t a[4],
                                         const uint32_t b[2]) {
    asm volatile("mma.sync.aligned.m16n8k16.row.col.f32.bf16.bf16.f32 "
                 "{%0,%1,%2,%3},{%4,%5,%6,%7},{%8,%9},{%0,%1,%2,%3};"
                 : "+f"(d[0]), "+f"(d[1]), "+f"(d[2]), "+f"(d[3])
                 : "r"(a[0]), "r"(a[1]), "r"(a[2]), "r"(a[3]),
                   "r"(b[0]), "r"(b[1]));
}
// packed f32x2 FMA (FFMA2)
__device__ __forceinline__ unsigned long long fma2(unsigned long long a,
                                                   unsigned long long b,
                                                   unsigned long long c) {
    unsigned long long d;
    asm("fma.rn.f32x2 %0, %1, %2, %3;" : "=l"(d) : "l"(a), "l"(b), "l"(c));
    return d;
}
__device__ __forceinline__ unsigned long long pk2(float x, float y) {
    unsigned long long r;
    asm("mov.b64 %0, {%1,%2};" : "=l"(r) : "f"(x), "f"(y));
    return r;
}
__device__ __forceinline__ float2 upk2(unsigned long long v) {
    float2 f;
    asm("mov.b64 {%0,%1}, %2;" : "=f"(f.x), "=f"(f.y) : "l"(v));
    return f;
}
#define CP_ASYNC(dst, src) \
    asm volatile("cp.async.cg.shared.global [%0], [%1], 16;" :: "r"(dst), "l"(src))
#define CP_COMMIT() asm volatile("cp.async.commit_group;" ::: "memory")

// ================= k1: norm_scale = cond @ w_cond.T + 1 =================
__global__ void k_cond(const float* __restrict__ cond,
                       const float* __restrict__ w_cond) {
    int w    = (blockIdx.x * blockDim.x + threadIdx.x) >> 5;
    int lane = threadIdx.x & 31;
    if (w >= 2 * DM) return;
    int n = w >> 9, c = w & 511;
    const float* cp = cond + n * CND;
    const float* wp = w_cond + c * CND;
    float s = 0.f;
    #pragma unroll 4
    for (int k = lane; k < CND; k += 32) s += cp[k] * wp[k];
    #pragma unroll
    for (int o = 16; o; o >>= 1) s += __shfl_xor_sync(~0u, s, o);
    if (!lane) g_nscale[w] = s + 1.0f;
}

// ===== k2: fused per-token RMS + scale + bf16 hi/lo convert of A =====
__global__ void k_prep_a(const float* __restrict__ x) {
    int wid = threadIdx.x >> 5, lane = threadIdx.x & 31;
    int row = blockIdx.x * 8 + wid;
    const float4* xp = (const float4*)(x + (size_t)row * DM);
    float4 vv[4];
    float s = 0.f;
    #pragma unroll
    for (int i = 0; i < 4; i++) {
        vv[i] = xp[i * 32 + lane];
        s += vv[i].x * vv[i].x + vv[i].y * vv[i].y +
             vv[i].z * vv[i].z + vv[i].w * vv[i].w;
    }
    #pragma unroll
    for (int o = 16; o; o >>= 1) s += __shfl_xor_sync(~0u, s, o);
    float rstd = rsqrtf(s * (1.0f / DM) + 1e-6f);
    const float* nsc = g_nscale + (row >> 10) * DM;
    #pragma unroll
    for (int i = 0; i < 4; i++) {
        int c0 = (i * 32 + lane) * 4;
        float a = vv[i].x * rstd * nsc[c0];
        float b = vv[i].y * rstd * nsc[c0 + 1];
        float c = vv[i].z * rstd * nsc[c0 + 2];
        float d = vv[i].w * rstd * nsc[c0 + 3];
        uint32_t h0, l0, h1, l1;
        split2(a, b, h0, l0);
        split2(c, d, h1, l1);
        *(uint2*)(g_ah + (size_t)row * DM + c0) = make_uint2(h0, h1);
        *(uint2*)(g_al + (size_t)row * DM + c0) = make_uint2(l0, l1);
    }
}

// ===== unified weight fp32 -> bf16 hi/lo converter (w_qkv then w_out) =====
__global__ void k_cvt_w(const float* __restrict__ wqkv,
                        const float* __restrict__ wout) {
    int idx = (blockIdx.x * 256 + threadIdx.x) * 4;
    if (idx >= 4 * DM * DM) return;
    const float* s = (idx < 3 * DM * DM) ? (wqkv + idx)
                                         : (wout + idx - 3 * DM * DM);
    float4 v = *(const float4*)s;
    uint32_t h0, l0, h1, l1;
    split2(v.x, v.y, h0, l0);
    split2(v.z, v.w, h1, l1);
    *(uint2*)(g_bh + idx) = make_uint2(h0, h1);
    *(uint2*)(g_bl + idx) = make_uint2(l0, l1);
}

// ====== bf16 split GEMM via mma.sync, cp.async 3-stage pipeline ======
// BM in {128,64}, BN=64, BK=32. 8 warps 4(m)x2(n), warp tile (BM/4)x32.
// TERMS=3: D = Ah*Bh + Al*Bh + Ah*Bl (fp32 fidelity). TERMS=1: D = Ah*Bh.
// MODE 0: scatter into g_q/g_k/g_v head-major. MODE 1: += skip -> outp.
template <int MODE, int BM, int TERMS>
__global__ __launch_bounds__(256, 3) void k_mm(const float* __restrict__ skip,
                                               float* __restrict__ outp) {
    constexpr int PLN_A  = BM * 64;           // bytes per A plane
    constexpr int NPA    = (TERMS == 3) ? 2 : 1;
    constexpr int OFF_B  = NPA * PLN_A;
    constexpr int STG    = OFF_B + ((TERMS == 3) ? 8192 : 4096);
    constexpr int MT     = BM / 64;           // m16-tiles per warp
    constexpr size_t BOFF = (MODE == 0) ? 0 : (size_t)3 * DM * DM;

    extern __shared__ char smem[];
    const uint32_t sb = smem_u32(smem);
    const int t = threadIdx.x, lane = t & 31, wid = t >> 5;
    const int m0 = blockIdx.y * BM, n0 = blockIdx.x * 64;
    const int mbase = (wid >> 1) * (BM / 4), nbase = (wid & 1) * 32;
    const int qy = lane >> 2, t4 = lane & 3;

    float acc[MT][4][4];
    #pragma unroll
    for (int i = 0; i < MT; i++)
        #pragma unroll
        for (int j = 0; j < 4; j++)
            #pragma unroll
            for (int r = 0; r < 4; r++) acc[i][j][r] = 0.f;

    auto issue = [&](int s) {
        if (s < 16) {
            int k0 = s * 32;
            uint32_t stb = sb + (s % 3) * STG;
            #pragma unroll
            for (int i = 0; i < BM / 64; i++) {   // A planes
                int rc = i * 256 + t;
                int row = rc >> 2, c = rc & 3;
                int phys = (c + (row >> 1)) & 3;
                uint32_t dst = stb + row * 64 + phys * 16;
                CP_ASYNC(dst, g_ah + (size_t)(m0 + row) * DM + k0 + c * 8);
                if (TERMS == 3)
                    CP_ASYNC(dst + PLN_A, g_al + (size_t)(m0 + row) * DM + k0 + c * 8);
            }
            {                                      // B planes (64 rows)
                int row = t >> 2, c = t & 3;
                int phys = (c + (row >> 1)) & 3;
                uint32_t dst = stb + OFF_B + row * 64 + phys * 16;
                CP_ASYNC(dst, g_bh + BOFF + (size_t)(n0 + row) * DM + k0 + c * 8);
                if (TERMS == 3)
                    CP_ASYNC(dst + 4096, g_bl + BOFF + (size_t)(n0 + row) * DM + k0 + c * 8);
            }
        }
        CP_COMMIT();
    };

    issue(0); issue(1);

    for (int it = 0; it < 16; ++it) {
        if (it < 15) asm volatile("cp.async.wait_group 1;" ::: "memory");
        else         asm volatile("cp.async.wait_group 0;" ::: "memory");
        __syncthreads();
        issue(it + 2);   // prefetch next-next stage before compute
        uint32_t stb = sb + (it % 3) * STG;
        #pragma unroll
        for (int kk = 0; kk < 2; ++kk) {
            uint32_t ah[MT][4], al[MT][4], bh[4][2], bl[4][2];
            #pragma unroll
            for (int mt = 0; mt < MT; ++mt) {
                int row = mbase + mt * 16 + (lane & 15);
                int c = kk * 2 + (lane >> 4);
                int phys = (c + (row >> 1)) & 3;
                uint32_t ad = stb + row * 64 + phys * 16;
                ldmx4(ah[mt], ad);
                if (TERMS == 3) ldmx4(al[mt], ad + PLN_A);
            }
            #pragma unroll
            for (int p = 0; p < 2; ++p) {
                int row = nbase + p * 16 + (lane & 15);
                int c = kk * 2 + (lane >> 4);
                int phys = (c + (row >> 1)) & 3;
                uint32_t ad = stb + OFF_B + row * 64 + phys * 16;
                uint32_t r4[4];
                ldmx4(r4, ad);
                bh[2 * p][0] = r4[0]; bh[2 * p][1] = r4[2];
                bh[2 * p + 1][0] = r4[1]; bh[2 * p + 1][1] = r4[3];
                if (TERMS == 3) {
                    ldmx4(r4, ad + 4096);
                    bl[2 * p][0] = r4[0]; bl[2 * p][1] = r4[2];
                    bl[2 * p + 1][0] = r4[1]; bl[2 * p + 1][1] = r4[3];
                }
            }
            #pragma unroll
            for (int mt = 0; mt < MT; ++mt)
                #pragma unroll
                for (int nt = 0; nt < 4; ++nt) mma_bf16(acc[mt][nt], ah[mt], bh[nt]);
            if (TERMS == 3) {
                #pragma unroll
                for (int mt = 0; mt < MT; ++mt)
                    #pragma unroll
                    for (int nt = 0; nt < 4; ++nt) mma_bf16(acc[mt][nt], al[mt], bh[nt]);
                #pragma unroll
                for (int mt = 0; mt < MT; ++mt)
                    #pragma unroll
                    for (int nt = 0; nt < 4; ++nt) mma_bf16(acc[mt][nt], ah[mt], bl[nt]);
            }
        }
    }

    // ---- epilogue ----
    const int nb = m0 >> 10;
    #pragma unroll
    for (int mt = 0; mt < MT; ++mt) {
        int r0 = m0 + mbase + mt * 16 + qy;
        #pragma unroll
        for (int nt = 0; nt < 4; ++nt) {
            int col = n0 + nbase + nt * 8 + 2 * t4;
            if (MODE == 0) {
                int part = col >> 9;
                int head = (col >> 6) & 7;
                int d0   = col & 63;
                int ij0  = r0 & 1023, ij1 = (r0 + 8) & 1023;
                float* dst = ((part == 0) ? g_q : (part == 1) ? g_k : g_v)
                             + ((size_t)(nb * NH + head) * 1024) * DH + d0;
                float2 v0 = {acc[mt][nt][0], acc[mt][nt][1]};
                float2 v1 = {acc[mt][nt][2], acc[mt][nt][3]};
                *(float2*)(dst + (size_t)ij0 * DH) = v0;
                *(float2*)(dst + (size_t)ij1 * DH) = v1;
            } else {
                float2 s0 = *(const float2*)(skip + (size_t)r0 * DM + col);
                float2 s1 = *(const float2*)(skip + (size_t)(r0 + 8) * DM + col);
                float2 v0 = {acc[mt][nt][0] + s0.x, acc[mt][nt][1] + s0.y};
                float2 v1 = {acc[mt][nt][2] + s1.x, acc[mt][nt][3] + s1.y};
                *(float2*)(outp + (size_t)r0 * DM + col)       = v0;
                *(float2*)(outp + (size_t)(r0 + 8) * DM + col) = v1;
            }
        }
    }
}

// ====== k4: merged per-head L2 norm + RoPE for q AND k (one warp both) ======
__global__ void k_rope(const float* __restrict__ pos,
                       const float* __restrict__ scale) {
    int w    = (blockIdx.x * blockDim.x + threadIdx.x) >> 5;
    int lane = threadIdx.x & 31;
    const int total = 2 * NH * 1024;   // 16384 (n,h,ij) rows
    if (w >= total) return;
    int n  = w >> 13;
    int h  = (w >> 10) & 7;
    int ij = w & 1023;
    float* pq = g_q + (size_t)w * DH;
    float* pk = g_k + (size_t)w * DH;

    float qa = pq[lane], qb = pq[lane + 32];
    float ka = pk[lane], kb = pk[lane + 32];
    float s1 = qa * qa + qb * qb;
    float s2 = ka * ka + kb * kb;
    #pragma unroll
    for (int o = 16; o; o >>= 1) {
        s1 += __shfl_xor_sync(~0u, s1, o);
        s2 += __shfl_xor_sync(~0u, s2, o);
    }
    float sq = sqrtf(scale[h]);
    float fq = sq * rsqrtf(s1 + 1e-6f);
    float fk = sq * rsqrtf(s2 + 1e-6f);
    qa *= fq; qb *= fq;
    ka *= fk; kb *= fk;

    int m = lane & 15;
    float freq = 3.14159265358979f * __expf((float)(m * 8 + h) * (2.302585092994046f / 128.0f));
    float th = pos[n * 1024 + ij] * freq;
    float sn, cs;
    __sincosf(th, &sn, &cs);
    float qpart = __shfl_xor_sync(~0u, qa, 16);
    float kpart = __shfl_xor_sync(~0u, ka, 16);
    float nqa = (lane < 16) ? (qa * cs - qpart * sn) : (qa * cs + qpart * sn);
    float nka = (lane < 16) ? (ka * cs - kpart * sn) : (ka * cs + kpart * sn);
    pq[lane]      = nqa;
    pq[lane + 32] = qb;
    pk[lane]      = nka;
    pk[lane + 32] = kb;
}

// ====== k5: 7x7 neighborhood attention (FFMA2 packed fp32) ======
__global__ __launch_bounds__(256, 2) void k_attn() {
    extern __shared__ float sm[];
    float* Ks = sm;
    float* Vs = sm + 196 * PAD;
    int b    = blockIdx.x;
    int tile = b & 15;
    int h    = (b >> 4) & 7;
    int n    = b >> 7;
    int i0 = (tile >> 2) * 8, j0 = (tile & 3) * 8;
    int rbase = min(max(i0 - 3, 0), 18);
    int cbase = min(max(j0 - 3, 0), 18);

    const float* kb = g_k + (size_t)((n * NH + h) * 1024) * DH;
    const float* vb = g_v + (size_t)((n * NH + h) * 1024) * DH;

    for (int idx = threadIdx.x; idx < 196 * 16; idx += 256) {
        int px = idx >> 4, u = idx & 15;
        int r = px / 14, cc = px - r * 14;
        int g = ((rbase + r) * 32 + cbase + cc) * 16 + u;
        ((float4*)(Ks + px * PAD))[u] = ((const float4*)kb)[g];
        ((float4*)(Vs + px * PAD))[u] = ((const float4*)vb)[g];
    }
    __syncthreads();

    int p = threadIdx.x >> 2, s = threadIdx.x & 3;
    int gi = i0 + (p >> 3), gj = j0 + (p & 7);
    int si = min(max(gi - 3, 0), 25) - rbase;
    int sj = min(max(gj - 3, 0), 25) - cbase;

    const float* qp = g_q + ((size_t)((n * NH + h) * 1024) + gi * 32 + gj) * DH + s * 16;
    ulonglong2 q01 = ((const ulonglong2*)qp)[0];
    ulonglong2 q23 = ((const ulonglong2*)qp)[1];
    ulonglong2 q45 = ((const ulonglong2*)qp)[2];
    ulonglong2 q67 = ((const ulonglong2*)qp)[3];

    float logit[49];
    #pragma unroll
    for (int a = 0; a < 7; a++) {
        #pragma unroll
        for (int bb = 0; bb < 7; bb++) {
            const ulonglong2* kp =
                (const ulonglong2*)(Ks + ((si + a) * 14 + sj + bb) * PAD + s * 16);
            ulonglong2 k01 = kp[0], k23 = kp[1], k45 = kp[2], k67 = kp[3];
            unsigned long long a2 = 0ull;
            a2 = fma2(q01.x, k01.x, a2);
            a2 = fma2(q01.y, k01.y, a2);
            a2 = fma2(q23.x, k23.x, a2);
            a2 = fma2(q23.y, k23.y, a2);
            a2 = fma2(q45.x, k45.x, a2);
            a2 = fma2(q45.y, k45.y, a2);
            a2 = fma2(q67.x, k67.x, a2);
            a2 = fma2(q67.y, k67.y, a2);
            float2 f = upk2(a2);
            float d = f.x + f.y;
            d += __shfl_xor_sync(~0u, d, 1);
            d += __shfl_xor_sync(~0u, d, 2);
            logit[a * 7 + bb] = d;
        }
    }

    float mx = -1e30f;
    #pragma unroll
    for (int i = 0; i < 49; i++) mx = fmaxf(mx, logit[i]);
    float sum = 0.f;
    #pragma unroll
    for (int i = 0; i < 49; i++) {
        float e = __expf(logit[i] - mx);
        logit[i] = e;
        sum += e;
    }
    float inv = 1.0f / sum;

    unsigned long long acc2[8];
    #pragma unroll
    for (int j = 0; j < 8; j++) acc2[j] = 0ull;
    #pragma unroll
    for (int a = 0; a < 7; a++) {
        #pragma unroll
        for (int bb = 0; bb < 7; bb++) {
            float wgt = logit[a * 7 + bb];
            unsigned long long w2 = pk2(wgt, wgt);
            const ulonglong2* vp =
                (const ulonglong2*)(Vs + ((si + a) * 14 + sj + bb) * PAD + s * 16);
            ulonglong2 v01 = vp[0], v23 = vp[1], v45 = vp[2], v67 = vp[3];
            acc2[0] = fma2(w2, v01.x, acc2[0]);
            acc2[1] = fma2(w2, v01.y, acc2[1]);
            acc2[2] = fma2(w2, v23.x, acc2[2]);
            acc2[3] = fma2(w2, v23.y, acc2[3]);
            acc2[4] = fma2(w2, v45.x, acc2[4]);
            acc2[5] = fma2(w2, v45.y, acc2[5]);
            acc2[6] = fma2(w2, v67.x, acc2[6]);
            acc2[7] = fma2(w2, v67.y, acc2[7]);
        }
    }

    // write attention output directly as bf16 hi plane (1-term out GEMM)
    size_t off = (size_t)(n * 1024 + gi * 32 + gj) * DM + h * DH + s * 16;
    uint32_t hw[8], lw[8];
    #pragma unroll
    for (int u = 0; u < 8; ++u) {
        float2 f = upk2(acc2[u]);
        split2(f.x * inv, f.y * inv, hw[u], lw[u]);
    }
    *(uint4*)(g_ah + off)     = make_uint4(hw[0], hw[1], hw[2], hw[3]);
    *(uint4*)(g_ah + off + 8) = make_uint4(hw[4], hw[5], hw[6], hw[7]);
}

// =========================== launch ===========================
extern "C" void kernel_launch(void* const* d_in, const int* in_sizes, int n_in,
                              void* d_out, int out_size) {
    const float* x      = (const float*)d_in[0];
    const float* pos    = (const float*)d_in[1];
    const float* cond   = (const float*)d_in[2];
    const float* w_cond = (const float*)d_in[3];
    const float* w_qkv  = (const float*)d_in[4];
    const float* scale  = (const float*)d_in[5];
    const float* w_out  = (const float*)d_in[6];
    float* out = (float*)d_out;

    const int attn_smem = 2 * 196 * PAD * 4;
    const int mm0_smem = 3 * (2 * 128 * 64 + 8192);  // 73728
    const int mm1_smem = 3 * (64 * 64 + 4096);       // 24576
    cudaFuncSetAttribute(k_attn, cudaFuncAttributeMaxDynamicSharedMemorySize,
                         attn_smem);
    cudaFuncSetAttribute((const void*)k_mm<0, 128, 3>,
                         cudaFuncAttributeMaxDynamicSharedMemorySize, mm0_smem);
    cudaFuncSetAttribute((const void*)k_mm<1, 64, 1>,
                         cudaFuncAttributeMaxDynamicSharedMemorySize, mm1_smem);

    k_cond<<<128, 256>>>(cond, w_cond);
    k_prep_a<<<256, 256>>>(x);
    k_cvt_w<<<1024, 256>>>(w_qkv, w_out);
    k_mm<0, 128, 3><<<dim3(24, 16), 256, mm0_smem>>>(nullptr, nullptr);
    k_rope<<<2048, 256>>>(pos, scale);
    k_attn<<<256, 256, attn_smem>>>();
    k_mm<1, 64, 1><<<dim3(8, 32), 256, mm1_smem>>>(x, out);
}

// round 17
// speedup vs baseline: 2.4834x; 1.0511x over previous
#include <cuda_runtime.h>
#include <cuda_bf16.h>
#include <math.h>
#include <stdint.h>

#define NTOK 2048
#define DM   512
#define NH   8
#define DH   64
#define CND  768
#define PAD  68

// -------- scratch (device globals; no allocation allowed) --------
__device__ float g_nscale[2 * DM];
__device__ __align__(16) float g_q[2 * NH * 1024 * DH];
__device__ __align__(16) float g_k[2 * NH * 1024 * DH];
__device__ __align__(16) float g_v[2 * NH * 1024 * DH];
// bf16 hi/lo planes (B: [w_qkv | w_out] at offset 3*DM*DM)
__device__ __align__(16) __nv_bfloat16 g_ah[NTOK * DM];
__device__ __align__(16) __nv_bfloat16 g_al[NTOK * DM];
__device__ __align__(16) __nv_bfloat16 g_bh[4 * DM * DM];
__device__ __align__(16) __nv_bfloat16 g_bl[4 * DM * DM];

// ---------------- helpers ----------------
__device__ __forceinline__ uint32_t smem_u32(const void* p) {
    uint32_t a;
    asm("{ .reg .u64 t; cvta.to.shared.u64 t, %1; cvt.u32.u64 %0, t; }"
        : "=r"(a) : "l"(p));
    return a;
}
__device__ __forceinline__ uint32_t pack2(__nv_bfloat16 a, __nv_bfloat16 b) {
    __nv_bfloat162 t = __halves2bfloat162(a, b);
    return *reinterpret_cast<uint32_t*>(&t);
}
__device__ __forceinline__ void split2(float a, float b, uint32_t& h, uint32_t& l) {
    __nv_bfloat16 ha = __float2bfloat16_rn(a), hb = __float2bfloat16_rn(b);
    h = pack2(ha, hb);
    l = pack2(__float2bfloat16_rn(a - __bfloat162float(ha)),
              __float2bfloat16_rn(b - __bfloat162float(hb)));
}
__device__ __forceinline__ void ldmx4(uint32_t r[4], uint32_t a) {
    asm volatile("ldmatrix.sync.aligned.m8n8.x4.shared.b16 {%0,%1,%2,%3}, [%4];"
                 : "=r"(r[0]), "=r"(r[1]), "=r"(r[2]), "=r"(r[3]) : "r"(a));
}
__device__ __forceinline__ void mma_bf16(float d[4], const uint32_t a[4],
                                         const uint32_t b[2]) {
    asm volatile("mma.sync.aligned.m16n8k16.row.col.f32.bf16.bf16.f32 "
                 "{%0,%1,%2,%3},{%4,%5,%6,%7},{%8,%9},{%0,%1,%2,%3};"
                 : "+f"(d[0]), "+f"(d[1]), "+f"(d[2]), "+f"(d[3])
                 : "r"(a[0]), "r"(a[1]), "r"(a[2]), "r"(a[3]),
                   "r"(b[0]), "r"(b[1]));
}
// packed f32x2 FMA (FFMA2)
__device__ __forceinline__ unsigned long long fma2(unsigned long long a,
                                                   unsigned long long b,
                                                   unsigned long long c) {
    unsigned long long d;
    asm("fma.rn.f32x2 %0, %1, %2, %3;" : "=l"(d) : "l"(a), "l"(b), "l"(c));
    return d;
}
__device__ __forceinline__ unsigned long long pk2(float x, float y) {
    unsigned long long r;
    asm("mov.b64 %0, {%1,%2};" : "=l"(r) : "f"(x), "f"(y));
    return r;
}
__device__ __forceinline__ float2 upk2(unsigned long long v) {
    float2 f;
    asm("mov.b64 {%0,%1}, %2;" : "=f"(f.x), "=f"(f.y) : "l"(v));
    return f;
}
#define CP_ASYNC(dst, src) \
    asm volatile("cp.async.cg.shared.global [%0], [%1], 16;" :: "r"(dst), "l"(src))
#define CP_COMMIT() asm volatile("cp.async.commit_group;" ::: "memory")

// ================= k1: norm_scale = cond @ w_cond.T + 1 =================
__global__ void k_cond(const float* __restrict__ cond,
                       const float* __restrict__ w_cond) {
    int w    = (blockIdx.x * blockDim.x + threadIdx.x) >> 5;
    int lane = threadIdx.x & 31;
    if (w >= 2 * DM) return;
    int n = w >> 9, c = w & 511;
    const float* cp = cond + n * CND;
    const float* wp = w_cond + c * CND;
    float s = 0.f;
    #pragma unroll 4
    for (int k = lane; k < CND; k += 32) s += cp[k] * wp[k];
    #pragma unroll
    for (int o = 16; o; o >>= 1) s += __shfl_xor_sync(~0u, s, o);
    if (!lane) g_nscale[w] = s + 1.0f;
}

// ===== k2: fused per-token RMS + scale + bf16 hi/lo convert of A =====
__global__ void k_prep_a(const float* __restrict__ x) {
    int wid = threadIdx.x >> 5, lane = threadIdx.x & 31;
    int row = blockIdx.x * 8 + wid;
    const float4* xp = (const float4*)(x + (size_t)row * DM);
    float4 vv[4];
    float s = 0.f;
    #pragma unroll
    for (int i = 0; i < 4; i++) {
        vv[i] = xp[i * 32 + lane];
        s += vv[i].x * vv[i].x + vv[i].y * vv[i].y +
             vv[i].z * vv[i].z + vv[i].w * vv[i].w;
    }
    #pragma unroll
    for (int o = 16; o; o >>= 1) s += __shfl_xor_sync(~0u, s, o);
    float rstd = rsqrtf(s * (1.0f / DM) + 1e-6f);
    const float* nsc = g_nscale + (row >> 10) * DM;
    #pragma unroll
    for (int i = 0; i < 4; i++) {
        int c0 = (i * 32 + lane) * 4;
        float a = vv[i].x * rstd * nsc[c0];
        float b = vv[i].y * rstd * nsc[c0 + 1];
        float c = vv[i].z * rstd * nsc[c0 + 2];
        float d = vv[i].w * rstd * nsc[c0 + 3];
        uint32_t h0, l0, h1, l1;
        split2(a, b, h0, l0);
        split2(c, d, h1, l1);
        *(uint2*)(g_ah + (size_t)row * DM + c0) = make_uint2(h0, h1);
        *(uint2*)(g_al + (size_t)row * DM + c0) = make_uint2(l0, l1);
    }
}

// ===== unified weight fp32 -> bf16 converter (w_qkv hi/lo, w_out hi only) =====
__global__ void k_cvt_w(const float* __restrict__ wqkv,
                        const float* __restrict__ wout) {
    int idx = (blockIdx.x * 256 + threadIdx.x) * 4;
    if (idx >= 4 * DM * DM) return;
    bool qkv = idx < 3 * DM * DM;
    const float* s = qkv ? (wqkv + idx) : (wout + idx - 3 * DM * DM);
    float4 v = *(const float4*)s;
    uint32_t h0, l0, h1, l1;
    split2(v.x, v.y, h0, l0);
    split2(v.z, v.w, h1, l1);
    *(uint2*)(g_bh + idx) = make_uint2(h0, h1);
    if (qkv) *(uint2*)(g_bl + idx) = make_uint2(l0, l1);
}

// ====== bf16 split GEMM via mma.sync, cp.async 3-stage pipeline ======
// BM in {128,64}, BN=64, BK=32. 8 warps 4(m)x2(n), warp tile (BM/4)x32.
// TERMS=3: D = Ah*Bh + Al*Bh + Ah*Bl (fp32 fidelity). TERMS=1: D = Ah*Bh.
// nb0: block-column offset (units of 64 cols) into the B matrix / output.
// MODE 0: scatter into g_q/g_k/g_v head-major. MODE 1: += skip -> outp.
template <int MODE, int BM, int TERMS>
__global__ __launch_bounds__(256, 3) void k_mm(const float* __restrict__ skip,
                                               float* __restrict__ outp,
                                               int nb0) {
    constexpr int PLN_A  = BM * 64;           // bytes per A plane
    constexpr int NPA    = (TERMS == 3) ? 2 : 1;
    constexpr int OFF_B  = NPA * PLN_A;
    constexpr int STG    = OFF_B + ((TERMS == 3) ? 8192 : 4096);
    constexpr int MT     = BM / 64;           // m16-tiles per warp
    constexpr size_t BOFF = (MODE == 0) ? 0 : (size_t)3 * DM * DM;

    extern __shared__ char smem[];
    const uint32_t sb = smem_u32(smem);
    const int t = threadIdx.x, lane = t & 31, wid = t >> 5;
    const int m0 = blockIdx.y * BM, n0 = (blockIdx.x + nb0) * 64;
    const int mbase = (wid >> 1) * (BM / 4), nbase = (wid & 1) * 32;
    const int qy = lane >> 2, t4 = lane & 3;

    float acc[MT][4][4];
    #pragma unroll
    for (int i = 0; i < MT; i++)
        #pragma unroll
        for (int j = 0; j < 4; j++)
            #pragma unroll
            for (int r = 0; r < 4; r++) acc[i][j][r] = 0.f;

    auto issue = [&](int s) {
        if (s < 16) {
            int k0 = s * 32;
            uint32_t stb = sb + (s % 3) * STG;
            #pragma unroll
            for (int i = 0; i < BM / 64; i++) {   // A planes
                int rc = i * 256 + t;
                int row = rc >> 2, c = rc & 3;
                int phys = (c + (row >> 1)) & 3;
                uint32_t dst = stb + row * 64 + phys * 16;
                CP_ASYNC(dst, g_ah + (size_t)(m0 + row) * DM + k0 + c * 8);
                if (TERMS == 3)
                    CP_ASYNC(dst + PLN_A, g_al + (size_t)(m0 + row) * DM + k0 + c * 8);
            }
            {                                      // B planes (64 rows)
                int row = t >> 2, c = t & 3;
                int phys = (c + (row >> 1)) & 3;
                uint32_t dst = stb + OFF_B + row * 64 + phys * 16;
                CP_ASYNC(dst, g_bh + BOFF + (size_t)(n0 + row) * DM + k0 + c * 8);
                if (TERMS == 3)
                    CP_ASYNC(dst + 4096, g_bl + BOFF + (size_t)(n0 + row) * DM + k0 + c * 8);
            }
        }
        CP_COMMIT();
    };

    issue(0); issue(1);

    for (int it = 0; it < 16; ++it) {
        if (it < 15) asm volatile("cp.async.wait_group 1;" ::: "memory");
        else         asm volatile("cp.async.wait_group 0;" ::: "memory");
        __syncthreads();
        uint32_t stb = sb + (it % 3) * STG;
        #pragma unroll
        for (int kk = 0; kk < 2; ++kk) {
            uint32_t ah[MT][4], al[MT][4], bh[4][2], bl[4][2];
            #pragma unroll
            for (int mt = 0; mt < MT; ++mt) {
                int row = mbase + mt * 16 + (lane & 15);
                int c = kk * 2 + (lane >> 4);
                int phys = (c + (row >> 1)) & 3;
                uint32_t ad = stb + row * 64 + phys * 16;
                ldmx4(ah[mt], ad);
                if (TERMS == 3) ldmx4(al[mt], ad + PLN_A);
            }
            #pragma unroll
            for (int p = 0; p < 2; ++p) {
                int row = nbase + p * 16 + (lane & 15);
                int c = kk * 2 + (lane >> 4);
                int phys = (c + (row >> 1)) & 3;
                uint32_t ad = stb + OFF_B + row * 64 + phys * 16;
                uint32_t r4[4];
                ldmx4(r4, ad);
                bh[2 * p][0] = r4[0]; bh[2 * p][1] = r4[2];
                bh[2 * p + 1][0] = r4[1]; bh[2 * p + 1][1] = r4[3];
                if (TERMS == 3) {
                    ldmx4(r4, ad + 4096);
                    bl[2 * p][0] = r4[0]; bl[2 * p][1] = r4[2];
                    bl[2 * p + 1][0] = r4[1]; bl[2 * p + 1][1] = r4[3];
                }
            }
            #pragma unroll
            for (int mt = 0; mt < MT; ++mt)
                #pragma unroll
                for (int nt = 0; nt < 4; ++nt) mma_bf16(acc[mt][nt], ah[mt], bh[nt]);
            if (TERMS == 3) {
                #pragma unroll
                for (int mt = 0; mt < MT; ++mt)
                    #pragma unroll
                    for (int nt = 0; nt < 4; ++nt) mma_bf16(acc[mt][nt], al[mt], bh[nt]);
                #pragma unroll
                for (int mt = 0; mt < MT; ++mt)
                    #pragma unroll
                    for (int nt = 0; nt < 4; ++nt) mma_bf16(acc[mt][nt], ah[mt], bl[nt]);
            }
        }
        issue(it + 2);
    }

    // ---- epilogue ----
    const int nb = m0 >> 10;
    #pragma unroll
    for (int mt = 0; mt < MT; ++mt) {
        int r0 = m0 + mbase + mt * 16 + qy;
        #pragma unroll
        for (int nt = 0; nt < 4; ++nt) {
            int col = n0 + nbase + nt * 8 + 2 * t4;
            if (MODE == 0) {
                int part = col >> 9;
                int head = (col >> 6) & 7;
                int d0   = col & 63;
                int ij0  = r0 & 1023, ij1 = (r0 + 8) & 1023;
                float* dst = ((part == 0) ? g_q : (part == 1) ? g_k : g_v)
                             + ((size_t)(nb * NH + head) * 1024) * DH + d0;
                float2 v0 = {acc[mt][nt][0], acc[mt][nt][1]};
                float2 v1 = {acc[mt][nt][2], acc[mt][nt][3]};
                *(float2*)(dst + (size_t)ij0 * DH) = v0;
                *(float2*)(dst + (size_t)ij1 * DH) = v1;
            } else {
                float2 s0 = *(const float2*)(skip + (size_t)r0 * DM + col);
                float2 s1 = *(const float2*)(skip + (size_t)(r0 + 8) * DM + col);
                float2 v0 = {acc[mt][nt][0] + s0.x, acc[mt][nt][1] + s0.y};
                float2 v1 = {acc[mt][nt][2] + s1.x, acc[mt][nt][3] + s1.y};
                *(float2*)(outp + (size_t)r0 * DM + col)       = v0;
                *(float2*)(outp + (size_t)(r0 + 8) * DM + col) = v1;
            }
        }
    }
}

// ====== k4: merged per-head L2 norm + RoPE for q AND k (one warp both) ======
__global__ void k_rope(const float* __restrict__ pos,
                       const float* __restrict__ scale) {
    int w    = (blockIdx.x * blockDim.x + threadIdx.x) >> 5;
    int lane = threadIdx.x & 31;
    const int total = 2 * NH * 1024;   // 16384 (n,h,ij) rows
    if (w >= total) return;
    int n  = w >> 13;
    int h  = (w >> 10) & 7;
    int ij = w & 1023;
    float* pq = g_q + (size_t)w * DH;
    float* pk = g_k + (size_t)w * DH;

    float qa = pq[lane], qb = pq[lane + 32];
    float ka = pk[lane], kb = pk[lane + 32];
    float s1 = qa * qa + qb * qb;
    float s2 = ka * ka + kb * kb;
    #pragma unroll
    for (int o = 16; o; o >>= 1) {
        s1 += __shfl_xor_sync(~0u, s1, o);
        s2 += __shfl_xor_sync(~0u, s2, o);
    }
    float sq = sqrtf(scale[h]);
    float fq = sq * rsqrtf(s1 + 1e-6f);
    float fk = sq * rsqrtf(s2 + 1e-6f);
    qa *= fq; qb *= fq;
    ka *= fk; kb *= fk;

    int m = lane & 15;
    float freq = 3.14159265358979f * __expf((float)(m * 8 + h) * (2.302585092994046f / 128.0f));
    float th = pos[n * 1024 + ij] * freq;
    float sn, cs;
    __sincosf(th, &sn, &cs);
    float qpart = __shfl_xor_sync(~0u, qa, 16);
    float kpart = __shfl_xor_sync(~0u, ka, 16);
    float nqa = (lane < 16) ? (qa * cs - qpart * sn) : (qa * cs + qpart * sn);
    float nka = (lane < 16) ? (ka * cs - kpart * sn) : (ka * cs + kpart * sn);
    pq[lane]      = nqa;
    pq[lane + 32] = qb;
    pk[lane]      = nka;
    pk[lane + 32] = kb;
}

// ====== k5: 7x7 neighborhood attention (FFMA2 packed fp32) ======
__global__ __launch_bounds__(256, 2) void k_attn() {
    extern __shared__ float sm[];
    float* Ks = sm;
    float* Vs = sm + 196 * PAD;
    int b    = blockIdx.x;
    int tile = b & 15;
    int h    = (b >> 4) & 7;
    int n    = b >> 7;
    int i0 = (tile >> 2) * 8, j0 = (tile & 3) * 8;
    int rbase = min(max(i0 - 3, 0), 18);
    int cbase = min(max(j0 - 3, 0), 18);

    const float* kb = g_k + (size_t)((n * NH + h) * 1024) * DH;
    const float* vb = g_v + (size_t)((n * NH + h) * 1024) * DH;

    for (int idx = threadIdx.x; idx < 196 * 16; idx += 256) {
        int px = idx >> 4, u = idx & 15;
        int r = px / 14, cc = px - r * 14;
        int g = ((rbase + r) * 32 + cbase + cc) * 16 + u;
        ((float4*)(Ks + px * PAD))[u] = ((const float4*)kb)[g];
        ((float4*)(Vs + px * PAD))[u] = ((const float4*)vb)[g];
    }
    __syncthreads();

    int p = threadIdx.x >> 2, s = threadIdx.x & 3;
    int gi = i0 + (p >> 3), gj = j0 + (p & 7);
    int si = min(max(gi - 3, 0), 25) - rbase;
    int sj = min(max(gj - 3, 0), 25) - cbase;

    const float* qp = g_q + ((size_t)((n * NH + h) * 1024) + gi * 32 + gj) * DH + s * 16;
    ulonglong2 q01 = ((const ulonglong2*)qp)[0];
    ulonglong2 q23 = ((const ulonglong2*)qp)[1];
    ulonglong2 q45 = ((const ulonglong2*)qp)[2];
    ulonglong2 q67 = ((const ulonglong2*)qp)[3];

    float logit[49];
    #pragma unroll
    for (int a = 0; a < 7; a++) {
        #pragma unroll
        for (int bb = 0; bb < 7; bb++) {
            const ulonglong2* kp =
                (const ulonglong2*)(Ks + ((si + a) * 14 + sj + bb) * PAD + s * 16);
            ulonglong2 k01 = kp[0], k23 = kp[1], k45 = kp[2], k67 = kp[3];
            unsigned long long a2 = 0ull;
            a2 = fma2(q01.x, k01.x, a2);
            a2 = fma2(q01.y, k01.y, a2);
            a2 = fma2(q23.x, k23.x, a2);
            a2 = fma2(q23.y, k23.y, a2);
            a2 = fma2(q45.x, k45.x, a2);
            a2 = fma2(q45.y, k45.y, a2);
            a2 = fma2(q67.x, k67.x, a2);
            a2 = fma2(q67.y, k67.y, a2);
            float2 f = upk2(a2);
            float d = f.x + f.y;
            d += __shfl_xor_sync(~0u, d, 1);
            d += __shfl_xor_sync(~0u, d, 2);
            logit[a * 7 + bb] = d;
        }
    }

    float mx = -1e30f;
    #pragma unroll
    for (int i = 0; i < 49; i++) mx = fmaxf(mx, logit[i]);
    float sum = 0.f;
    #pragma unroll
    for (int i = 0; i < 49; i++) {
        float e = __expf(logit[i] - mx);
        logit[i] = e;
        sum += e;
    }
    float inv = 1.0f / sum;

    unsigned long long acc2[8];
    #pragma unroll
    for (int j = 0; j < 8; j++) acc2[j] = 0ull;
    #pragma unroll
    for (int a = 0; a < 7; a++) {
        #pragma unroll
        for (int bb = 0; bb < 7; bb++) {
            float wgt = logit[a * 7 + bb];
            unsigned long long w2 = pk2(wgt, wgt);
            const ulonglong2* vp =
                (const ulonglong2*)(Vs + ((si + a) * 14 + sj + bb) * PAD + s * 16);
            ulonglong2 v01 = vp[0], v23 = vp[1], v45 = vp[2], v67 = vp[3];
            acc2[0] = fma2(w2, v01.x, acc2[0]);
            acc2[1] = fma2(w2, v01.y, acc2[1]);
            acc2[2] = fma2(w2, v23.x, acc2[2]);
            acc2[3] = fma2(w2, v23.y, acc2[3]);
            acc2[4] = fma2(w2, v45.x, acc2[4]);
            acc2[5] = fma2(w2, v45.y, acc2[5]);
            acc2[6] = fma2(w2, v67.x, acc2[6]);
            acc2[7] = fma2(w2, v67.y, acc2[7]);
        }
    }

    // write attention output directly as bf16 hi plane (1-term out GEMM)
    size_t off = (size_t)(n * 1024 + gi * 32 + gj) * DM + h * DH + s * 16;
    uint32_t hw[8];
    #pragma unroll
    for (int u = 0; u < 8; ++u) {
        float2 f = upk2(acc2[u]);
        hw[u] = pack2(__float2bfloat16_rn(f.x * inv), __float2bfloat16_rn(f.y * inv));
    }
    *(uint4*)(g_ah + off)     = make_uint4(hw[0], hw[1], hw[2], hw[3]);
    *(uint4*)(g_ah + off + 8) = make_uint4(hw[4], hw[5], hw[6], hw[7]);
}

// =========================== launch ===========================
extern "C" void kernel_launch(void* const* d_in, const int* in_sizes, int n_in,
                              void* d_out, int out_size) {
    const float* x      = (const float*)d_in[0];
    const float* pos    = (const float*)d_in[1];
    const float* cond   = (const float*)d_in[2];
    const float* w_cond = (const float*)d_in[3];
    const float* w_qkv  = (const float*)d_in[4];
    const float* scale  = (const float*)d_in[5];
    const float* w_out  = (const float*)d_in[6];
    float* out = (float*)d_out;

    const int attn_smem = 2 * 196 * PAD * 4;
    const int mm3_smem  = 3 * (2 * 128 * 64 + 8192);  // 73728 (TERMS=3, BM=128)
    const int mmv_smem  = 3 * (128 * 64 + 4096);      // 36864 (TERMS=1, BM=128)
    const int mm1_smem  = 3 * (64 * 64 + 4096);       // 24576 (TERMS=1, BM=64)
    cudaFuncSetAttribute(k_attn, cudaFuncAttributeMaxDynamicSharedMemorySize,
                         attn_smem);
    cudaFuncSetAttribute((const void*)k_mm<0, 128, 3>,
                         cudaFuncAttributeMaxDynamicSharedMemorySize, mm3_smem);
    cudaFuncSetAttribute((const void*)k_mm<0, 128, 1>,
                         cudaFuncAttributeMaxDynamicSharedMemorySize, mmv_smem);
    cudaFuncSetAttribute((const void*)k_mm<1, 64, 1>,
                         cudaFuncAttributeMaxDynamicSharedMemorySize, mm1_smem);

    k_cond<<<128, 256>>>(cond, w_cond);
    k_prep_a<<<256, 256>>>(x);
    k_cvt_w<<<1024, 256>>>(w_qkv, w_out);
    // q,k columns: full 3-term fidelity; v columns: 1-term bf16
    k_mm<0, 128, 3><<<dim3(16, 16), 256, mm3_smem>>>(nullptr, nullptr, 0);
    k_mm<0, 128, 1><<<dim3(8, 16), 256, mmv_smem>>>(nullptr, nullptr, 16);
    k_rope<<<2048, 256>>>(pos, scale);
    k_attn<<<256, 256, attn_smem>>>();
    k_mm<1, 64, 1><<<dim3(8, 32), 256, mm1_smem>>>(x, out, 0);
}